// round 10
// baseline (speedup 1.0000x reference)
#include <cuda_runtime.h>
#include <cuda_fp16.h>
#include <cstdint>
#include <math.h>

// ---------------------------------------------------------------------------
// CrossModalFusion, fp16 mma.sync (m16n8k16, f32 acc).
// R10: R8 GEMM config frozen; softmax exp moved off MUFU onto FMA pipe.
// B=32, Sr=Sp=2048, D=400, H=512
// ---------------------------------------------------------------------------
#define B_   32
#define SR_  2048
#define SP_  2048
#define DIM_ 400
#define HID_ 512
#define MROWS (B_ * SR_)          // 65536

__device__ __half g_q [(size_t)MROWS * HID_];
__device__ __half g_k [(size_t)MROWS * HID_];
__device__ __half g_vt[(size_t)MROWS * HID_];     // [B][H][Sp]
__device__ __half g_sh[(size_t)B_ * SR_ * SP_];   // scores (half)
__device__ __half g_ph[(size_t)B_ * SR_ * SP_];   // probs (half)
__device__ __half g_o [(size_t)MROWS * HID_];
__device__ float  g_p [(size_t)MROWS * DIM_];
__device__ __half g_wt[4 * 512 * 400];            // WqT | WkT | WvT | WpT
__device__ __half g_rgbh [(size_t)MROWS * DIM_];
__device__ __half g_poseh[(size_t)MROWS * DIM_];

__device__ __forceinline__ uint32_t smem_u32(const void* p) {
    uint32_t a;
    asm("{ .reg .u64 t; cvta.to.shared.u64 t, %1; cvt.u32.u64 %0, t; }" : "=r"(a) : "l"(p));
    return a;
}
__device__ __forceinline__ void cp16(uint32_t dst, const void* src, int bytes) {
    asm volatile("cp.async.cg.shared.global [%0], [%1], 16, %2;"
                 :: "r"(dst), "l"(src), "r"(bytes));
}
#define LDSM_X4(r0, r1, r2, r3, addr)                                         \
    asm volatile("ldmatrix.sync.aligned.m8n8.x4.shared.b16 {%0,%1,%2,%3}, [%4];" \
                 : "=r"(r0), "=r"(r1), "=r"(r2), "=r"(r3) : "r"(addr))

#define MMA_F16(c, a0, a1, a2, a3, b0, b1)                                    \
    asm volatile("mma.sync.aligned.m16n8k16.row.col.f32.f16.f16.f32 "         \
                 "{%0,%1,%2,%3}, {%4,%5,%6,%7}, {%8,%9}, {%0,%1,%2,%3};"      \
                 : "+f"((c)[0]), "+f"((c)[1]), "+f"((c)[2]), "+f"((c)[3])     \
                 : "r"(a0), "r"(a1), "r"(a2), "r"(a3), "r"(b0), "r"(b1))

// FMA-pipe exp(x) for x <= 0 (softmax after max-subtraction).
// rint via magic constant; 2^f Taylor deg-5 on [-0.5,0.5] (abs err ~2.4e-6);
// exponent injected via integer add on the float bits. No MUFU.
__device__ __forceinline__ float fexp(float x) {
    x = fmaxf(x, -60.0f);                        // keep result normal
    float y = x * 1.4426950408889634f;           // log2(e)
    float km = y + 12582912.0f;                  // 2^23 + 2^22 magic
    int   n  = __float_as_int(km) - 0x4B400000;  // rint(y) as int
    float f  = y - (km - 12582912.0f);           // frac in [-0.5, 0.5]
    float p = 1.3333558e-3f;
    p = fmaf(p, f, 9.6181291e-3f);
    p = fmaf(p, f, 5.5504109e-2f);
    p = fmaf(p, f, 2.4022651e-1f);
    p = fmaf(p, f, 6.9314718e-1f);
    p = fmaf(p, f, 1.0f);
    return __int_as_float(__float_as_int(p) + (n << 23));
}

// ---------------------------------------------------------------------------
// fp16 GEMM: C[M,N] = alpha*A[M,K]@B[N,K]^T (+bias), f32 acc.
// CTA tile 128x128, 8 warps (warp tile 64x32), BK=64 halves, 3-stage cp.async.
// MODE 0: plain store (OUT_HALF: half2 vs float2).
// MODE 2: fused k|v — n0<512: k store (ld 512, bias); n0>=512: vT via smem (bias2).
// ---------------------------------------------------------------------------
template <int MODE, int OUT_HALF>
__global__ __launch_bounds__(256, 2)
void h16_mma_gemm(const __half* __restrict__ A, const __half* __restrict__ Bm,
                  const float* __restrict__ bias, const float* __restrict__ bias2,
                  void* __restrict__ Cv, __half* __restrict__ C2,
                  int N, int K,
                  long long sA, long long sB, long long sC, float alpha)
{
    extern __shared__ char smem[];
    const uint32_t sb = smem_u32(smem);
    const int tid = threadIdx.x;
    const int wid = tid >> 5, lane = tid & 31;
    const int warp_m = wid & 1;
    const int warp_n = wid >> 1;

    A  += (long long)blockIdx.z * sA;
    Bm += (long long)blockIdx.z * sB;
    const int m0 = blockIdx.y * 128;
    const int n0 = blockIdx.x * 128;
    const int KT = (K + 63) >> 6;

    auto load_stage = [&](int kt, int s) {
        const int k0 = kt << 6;
        const uint32_t base = sb + (uint32_t)s * 32768u;
#pragma unroll
        for (int i = 0; i < 4; i++) {
            int e = tid + (i << 8);
            int row = e >> 3, c = e & 7;
            int kk = k0 + (c << 3);
            uint32_t off = (uint32_t)(row * 128) + (uint32_t)((c ^ (row & 7)) << 4);
            const bool kin = kk < K;
            const __half* ga = A + (long long)(m0 + row) * K + kk;
            cp16(base + off, ga, kin ? 16 : 0);
            const bool bin = kin && (n0 + row) < N;
            const __half* gb = Bm + (long long)(n0 + row) * K + kk;
            cp16(base + 16384u + off, bin ? gb : Bm, bin ? 16 : 0);
        }
        asm volatile("cp.async.commit_group;" ::: "memory");
    };

    float acc[4][4][4];
#pragma unroll
    for (int i = 0; i < 4; i++)
#pragma unroll
        for (int j = 0; j < 4; j++)
#pragma unroll
            for (int k = 0; k < 4; k++) acc[i][j][k] = 0.f;

    const int t = lane >> 3, r = lane & 7;
    const uint32_t a_row = (uint32_t)(warp_m * 64 + (t & 1) * 8 + r);
    const uint32_t b_row = (uint32_t)(warp_n * 32 + (t & 1) * 8 + r);
    const uint32_t chb   = (uint32_t)(t >> 1);

    load_stage(0, 0);
    if (KT > 1) load_stage(1, 1);

    for (int kt = 0; kt < KT; kt++) {
        if (kt + 1 < KT) asm volatile("cp.async.wait_group 1;" ::: "memory");
        else             asm volatile("cp.async.wait_group 0;" ::: "memory");
        __syncthreads();
        if (kt + 2 < KT) load_stage(kt + 2, (kt + 2) % 3);

        const uint32_t baseA = sb + (uint32_t)(kt % 3) * 32768u;
        const uint32_t baseB = baseA + 16384u;

#pragma unroll
        for (int ks = 0; ks < 4; ks++) {
            uint32_t a[4][4], b[2][4];
#pragma unroll
            for (int mi = 0; mi < 4; mi++) {
                uint32_t addr = baseA + (a_row + mi * 16) * 128u
                              + ((((ks * 2) + chb) ^ (uint32_t)r) << 4);
                LDSM_X4(a[mi][0], a[mi][1], a[mi][2], a[mi][3], addr);
            }
#pragma unroll
            for (int j = 0; j < 2; j++) {
                uint32_t addr = baseB + (b_row + j * 16) * 128u
                              + ((((ks * 2) + chb) ^ (uint32_t)r) << 4);
                LDSM_X4(b[j][0], b[j][1], b[j][2], b[j][3], addr);
            }
#pragma unroll
            for (int mi = 0; mi < 4; mi++)
#pragma unroll
                for (int ni = 0; ni < 4; ni++)
                    MMA_F16(acc[mi][ni], a[mi][0], a[mi][1], a[mi][2], a[mi][3],
                            b[ni >> 1][ni & 1], b[ni >> 1][(ni & 1) + 2]);
        }
    }

    const int m_base_l = warp_m * 64;
    const int n_base_l = warp_n * 32;
    const int row_in = lane >> 2;
    const int col_in = (lane & 3) * 2;

    const bool k_side = (MODE != 2) || (n0 < 512);

    if (MODE == 0 || k_side) {
        const int ldC = (MODE == 2) ? 512 : N;
#pragma unroll
        for (int mi = 0; mi < 4; mi++) {
            const int gm0 = m0 + m_base_l + mi * 16 + row_in;
#pragma unroll
            for (int ni = 0; ni < 4; ni++) {
                const int gn = n0 + n_base_l + ni * 8 + col_in;
                if (gn < N) {
                    float b0 = bias ? __ldg(&bias[gn]) : 0.f;
                    float b1 = bias ? __ldg(&bias[gn + 1]) : 0.f;
                    float v00 = acc[mi][ni][0] * alpha + b0;
                    float v01 = acc[mi][ni][1] * alpha + b1;
                    float v10 = acc[mi][ni][2] * alpha + b0;
                    float v11 = acc[mi][ni][3] * alpha + b1;
                    if (OUT_HALF) {
                        __half* C = (__half*)Cv + (long long)blockIdx.z * sC;
                        *reinterpret_cast<__half2*>(&C[(long long)gm0 * ldC + gn]) =
                            __floats2half2_rn(v00, v01);
                        *reinterpret_cast<__half2*>(&C[(long long)(gm0 + 8) * ldC + gn]) =
                            __floats2half2_rn(v10, v11);
                    } else {
                        float* C = (float*)Cv + (long long)blockIdx.z * sC;
                        *reinterpret_cast<float2*>(&C[(long long)gm0 * ldC + gn]) =
                            make_float2(v00, v01);
                        *reinterpret_cast<float2*>(&C[(long long)(gm0 + 8) * ldC + gn]) =
                            make_float2(v10, v11);
                    }
                }
            }
        }
    } else {
        // v side: vT[b][h][p], h = gn - 512. Stage [n][m] half tile in smem.
        __syncthreads();
        __half* sm = reinterpret_cast<__half*>(smem);
        const int PAD = 136;
        const int h0 = n0 - 512;
#pragma unroll
        for (int mi = 0; mi < 4; mi++) {
            const int ml = m_base_l + mi * 16 + row_in;
#pragma unroll
            for (int ni = 0; ni < 4; ni++) {
                const int nl = n_base_l + ni * 8 + col_in;
                float b0 = bias2 ? __ldg(&bias2[h0 + nl]) : 0.f;
                float b1 = bias2 ? __ldg(&bias2[h0 + nl + 1]) : 0.f;
                sm[nl * PAD + ml]           = __float2half_rn(acc[mi][ni][0] + b0);
                sm[(nl + 1) * PAD + ml]     = __float2half_rn(acc[mi][ni][1] + b1);
                sm[nl * PAD + ml + 8]       = __float2half_rn(acc[mi][ni][2] + b0);
                sm[(nl + 1) * PAD + ml + 8] = __float2half_rn(acc[mi][ni][3] + b1);
            }
        }
        __syncthreads();
        const long long obase = ((long long)(m0 >> 11) << 20) + (m0 & 2047);
#pragma unroll
        for (int pass = 0; pass < 8; pass++) {
            int chunk = pass * 256 + tid;
            int n = chunk >> 4;
            int mc = (chunk & 15) << 3;
            uint4 v = *reinterpret_cast<uint4*>(&sm[n * PAD + mc]);
            *reinterpret_cast<uint4*>(&C2[obase + ((long long)(h0 + n) << 11) + mc]) = v;
        }
    }
}

// ---------------------------------------------------------------------------
// rgb & pose -> half copies
// ---------------------------------------------------------------------------
__global__ __launch_bounds__(256)
void prep_half(const float* __restrict__ rgb, const float* __restrict__ pose,
               __half* __restrict__ rgbh, __half* __restrict__ poseh)
{
    const long long NEL4 = (long long)MROWS * DIM_ / 4;
    long long idx = (long long)blockIdx.x * 256 + threadIdx.x;
    const float* src; __half* dst; long long j;
    if (idx < NEL4)          { src = rgb;  dst = rgbh;  j = idx; }
    else if (idx < 2 * NEL4) { src = pose; dst = poseh; j = idx - NEL4; }
    else return;
    float4 v = reinterpret_cast<const float4*>(src)[j];
    __half2 h0 = __floats2half2_rn(v.x, v.y);
    __half2 h1 = __floats2half2_rn(v.z, v.w);
    reinterpret_cast<uint2*>(dst)[j] = make_uint2(
        *reinterpret_cast<uint32_t*>(&h0), *reinterpret_cast<uint32_t*>(&h1));
}

// ---------------------------------------------------------------------------
// Weight transpose -> half: WqT/WkT/WvT [512,400]; WpT [400,512]
// ---------------------------------------------------------------------------
__global__ __launch_bounds__(256)
void transpose_w(const float* __restrict__ Wq, const float* __restrict__ Wk,
                 const float* __restrict__ Wv, const float* __restrict__ Wp,
                 __half* __restrict__ out)
{
    const int SZ = 512 * 400;
    int idx = blockIdx.x * 256 + threadIdx.x;
    if (idx < 3 * SZ) {
        int w = idx / SZ, rr = idx % SZ;
        int h = rr / 400, dd = rr % 400;
        const float* W = (w == 0) ? Wq : (w == 1) ? Wk : Wv;
        out[idx] = __float2half_rn(W[dd * 512 + h]);
    } else if (idx < 4 * SZ) {
        int rr = idx - 3 * SZ;
        int n = rr / 512, kk = rr % 512;
        out[idx] = __float2half_rn(Wp[kk * 400 + n]);
    }
}

// ---------------------------------------------------------------------------
// Row softmax: 2048 half -> half. 256 thr/row, shuffle reductions, FMA exp.
// ---------------------------------------------------------------------------
__global__ __launch_bounds__(256)
void softmax_rows_kernel(const __half* __restrict__ S, __half* __restrict__ P)
{
    const uint4* row = reinterpret_cast<const uint4*>(S + (long long)blockIdx.x * SP_);
    uint4* prow = reinterpret_cast<uint4*>(P + (long long)blockIdx.x * SP_);
    const int tid = threadIdx.x;
    const int wid = tid >> 5, lane = tid & 31;

    uint4 raw = row[tid];
    float v[8];
    {
        __half2* h = reinterpret_cast<__half2*>(&raw);
#pragma unroll
        for (int i = 0; i < 4; i++) {
            float2 f = __half22float2(h[i]);
            v[2 * i] = f.x; v[2 * i + 1] = f.y;
        }
    }
    float mx = v[0];
#pragma unroll
    for (int i = 1; i < 8; i++) mx = fmaxf(mx, v[i]);
#pragma unroll
    for (int s = 16; s > 0; s >>= 1)
        mx = fmaxf(mx, __shfl_xor_sync(0xFFFFFFFFu, mx, s));

    __shared__ float red[8];
    if (lane == 0) red[wid] = mx;
    __syncthreads();
    {
        float m = red[lane & 7];
#pragma unroll
        for (int s = 4; s > 0; s >>= 1)
            m = fmaxf(m, __shfl_xor_sync(0xFFFFFFFFu, m, s));
        mx = m;
    }

    float sum = 0.f;
#pragma unroll
    for (int i = 0; i < 8; i++) { v[i] = fexp(v[i] - mx); sum += v[i]; }
#pragma unroll
    for (int s = 16; s > 0; s >>= 1)
        sum += __shfl_xor_sync(0xFFFFFFFFu, sum, s);
    __syncthreads();
    if (lane == 0) red[wid] = sum;
    __syncthreads();
    {
        float sm = red[lane & 7];
#pragma unroll
        for (int s = 4; s > 0; s >>= 1)
            sm += __shfl_xor_sync(0xFFFFFFFFu, sm, s);
        sum = sm;
    }
    const float inv = 1.f / sum;

    uint4 outw;
    __half2* oh = reinterpret_cast<__half2*>(&outw);
#pragma unroll
    for (int i = 0; i < 4; i++)
        oh[i] = __floats2half2_rn(v[2 * i] * inv, v[2 * i + 1] * inv);
    prow[tid] = outw;
}

// ---------------------------------------------------------------------------
// x = rgb + gate*proj ; out = LN(x)*gamma + beta
// ---------------------------------------------------------------------------
__global__ __launch_bounds__(256)
void residual_ln_kernel(const float* __restrict__ proj, const float* __restrict__ rgb,
                        const float* __restrict__ gamma, const float* __restrict__ beta,
                        const float* __restrict__ gate, float* __restrict__ out)
{
    const long long row = blockIdx.x;
    const float g = gate[0];
    const float* pr = proj + row * DIM_;
    const float* rr = rgb + row * DIM_;
    float* orow = out + row * DIM_;
    const int tid = threadIdx.x;
    const int i1 = tid + 256;
    const bool has1 = (i1 < DIM_);

    float x0 = rr[tid] + g * pr[tid];
    float x1 = has1 ? (rr[i1] + g * pr[i1]) : 0.f;

    __shared__ float rs[256], rs2[256];
    rs[tid] = x0 + x1;
    rs2[tid] = x0 * x0 + x1 * x1;
    __syncthreads();
#pragma unroll
    for (int s = 128; s > 0; s >>= 1) {
        if (tid < s) { rs[tid] += rs[tid + s]; rs2[tid] += rs2[tid + s]; }
        __syncthreads();
    }
    const float mean = rs[0] * (1.f / DIM_);
    const float var  = rs2[0] * (1.f / DIM_) - mean * mean;
    const float inv  = rsqrtf(var + 1e-5f);

    orow[tid] = (x0 - mean) * inv * gamma[tid] + beta[tid];
    if (has1) orow[i1] = (x1 - mean) * inv * gamma[i1] + beta[i1];
}

// ---------------------------------------------------------------------------
// Launch
// ---------------------------------------------------------------------------
extern "C" void kernel_launch(void* const* d_in, const int* in_sizes, int n_in,
                              void* d_out, int out_size)
{
    const float* rgb  = (const float*)d_in[0];
    const float* pose = (const float*)d_in[1];
    const float* Wq   = (const float*)d_in[2];
    const float* bq   = (const float*)d_in[3];
    const float* Wk   = (const float*)d_in[4];
    const float* bk   = (const float*)d_in[5];
    const float* Wv   = (const float*)d_in[6];
    const float* bv   = (const float*)d_in[7];
    const float* Wp   = (const float*)d_in[8];
    const float* bp   = (const float*)d_in[9];
    const float* lng  = (const float*)d_in[10];
    const float* lnb  = (const float*)d_in[11];
    const float* gate = (const float*)d_in[12];
    float* out = (float*)d_out;

    __half *q, *k, *vt, *sh, *ph, *o, *wt, *rgbh, *poseh;
    float *p;
    cudaGetSymbolAddress((void**)&q,  g_q);
    cudaGetSymbolAddress((void**)&k,  g_k);
    cudaGetSymbolAddress((void**)&vt, g_vt);
    cudaGetSymbolAddress((void**)&sh, g_sh);
    cudaGetSymbolAddress((void**)&ph, g_ph);
    cudaGetSymbolAddress((void**)&o,  g_o);
    cudaGetSymbolAddress((void**)&p,  g_p);
    cudaGetSymbolAddress((void**)&wt, g_wt);
    cudaGetSymbolAddress((void**)&rgbh,  g_rgbh);
    cudaGetSymbolAddress((void**)&poseh, g_poseh);

    const int SMEM = 3 * 32768;        // 96 KB
    cudaFuncSetAttribute(h16_mma_gemm<0,1>, cudaFuncAttributeMaxDynamicSharedMemorySize, SMEM);
    cudaFuncSetAttribute(h16_mma_gemm<0,0>, cudaFuncAttributeMaxDynamicSharedMemorySize, SMEM);
    cudaFuncSetAttribute(h16_mma_gemm<2,1>, cudaFuncAttributeMaxDynamicSharedMemorySize, SMEM);

    const int WSZ = 512 * 400;

    // 0. prep
    {
        long long n4 = 2LL * MROWS * DIM_ / 4;
        prep_half<<<(unsigned)((n4 + 255) / 256), 256>>>(rgb, pose, rgbh, poseh);
        transpose_w<<<(4 * WSZ + 255) / 256, 256>>>(Wq, Wk, Wv, Wp, wt);
    }

    // 1. q projection -> half
    {
        dim3 grid(4, MROWS / 128, 1);
        h16_mma_gemm<0,1><<<grid, 256, SMEM>>>(
            rgbh, wt, bq, nullptr, q, nullptr, HID_, DIM_, 0, 0, 0, 1.f);
    }
    // 2. fused k|v projection: B = [WkT;WvT] (1024x400); k plain, v -> vT
    {
        dim3 grid(8, MROWS / 128, 1);
        h16_mma_gemm<2,1><<<grid, 256, SMEM>>>(
            poseh, wt + WSZ, bk, bv, k, vt, 1024, DIM_, 0, 0, 0, 1.f);
    }
    // 3. scores = q @ k^T / sqrt(512) -> half, batched
    {
        dim3 grid(SP_ / 128, SR_ / 128, B_);
        h16_mma_gemm<0,1><<<grid, 256, SMEM>>>(
            q, k, nullptr, nullptr, sh, nullptr, SP_, HID_,
            (long long)SR_ * HID_, (long long)SP_ * HID_,
            (long long)SR_ * SP_, 0.044194173824159216f);
    }
    // 4. softmax half -> half (FMA exp)
    softmax_rows_kernel<<<B_ * SR_, 256>>>(sh, ph);

    // 5. O = probs @ v (B = vT [H][Sp]) -> half, batched
    {
        dim3 grid(HID_ / 128, SR_ / 128, B_);
        h16_mma_gemm<0,1><<<grid, 256, SMEM>>>(
            ph, vt, nullptr, nullptr, o, nullptr, HID_, SP_,
            (long long)SR_ * SP_, (long long)HID_ * SP_,
            (long long)SR_ * HID_, 1.f);
    }
    // 6. proj = O @ Wp + bp -> fp32
    {
        dim3 grid((DIM_ + 127) / 128, MROWS / 128, 1);
        h16_mma_gemm<0,0><<<grid, 256, SMEM>>>(
            o, wt + 3 * WSZ, bp, nullptr, p, nullptr, DIM_, HID_, 0, 0, 0, 1.f);
    }
    // 7. residual + LayerNorm
    residual_ln_kernel<<<MROWS, 256>>>(p, rgb, lng, lnb, gate, out);
}

// round 11
// speedup vs baseline: 1.0244x; 1.0244x over previous
#include <cuda_runtime.h>
#include <cuda_fp16.h>
#include <cstdint>
#include <math.h>

// ---------------------------------------------------------------------------
// CrossModalFusion, fp16 mma.sync (m16n8k16, f32 acc).
// R11: softmax fused into GEMM epilogues (exp in scores epilogue, per-row
// 1/sum scale in attn-v epilogue), warp-per-row sum kernel in between.
// B=32, Sr=Sp=2048, D=400, H=512
// ---------------------------------------------------------------------------
#define B_   32
#define SR_  2048
#define SP_  2048
#define DIM_ 400
#define HID_ 512
#define MROWS (B_ * SR_)          // 65536

__device__ __half g_q [(size_t)MROWS * HID_];
__device__ __half g_k [(size_t)MROWS * HID_];
__device__ __half g_vt[(size_t)MROWS * HID_];     // [B][H][Sp]
__device__ __half g_pu[(size_t)B_ * SR_ * SP_];   // unnormalized probs (half)
__device__ float  g_inv[(size_t)MROWS];           // 1/rowsum
__device__ __half g_o [(size_t)MROWS * HID_];
__device__ float  g_p [(size_t)MROWS * DIM_];
__device__ __half g_wt[4 * 512 * 400];            // WqT | WkT | WvT | WpT
__device__ __half g_rgbh [(size_t)MROWS * DIM_];
__device__ __half g_poseh[(size_t)MROWS * DIM_];

__device__ __forceinline__ uint32_t smem_u32(const void* p) {
    uint32_t a;
    asm("{ .reg .u64 t; cvta.to.shared.u64 t, %1; cvt.u32.u64 %0, t; }" : "=r"(a) : "l"(p));
    return a;
}
__device__ __forceinline__ void cp16(uint32_t dst, const void* src, int bytes) {
    asm volatile("cp.async.cg.shared.global [%0], [%1], 16, %2;"
                 :: "r"(dst), "l"(src), "r"(bytes));
}
#define LDSM_X4(r0, r1, r2, r3, addr)                                         \
    asm volatile("ldmatrix.sync.aligned.m8n8.x4.shared.b16 {%0,%1,%2,%3}, [%4];" \
                 : "=r"(r0), "=r"(r1), "=r"(r2), "=r"(r3) : "r"(addr))

#define MMA_F16(c, a0, a1, a2, a3, b0, b1)                                    \
    asm volatile("mma.sync.aligned.m16n8k16.row.col.f32.f16.f16.f32 "         \
                 "{%0,%1,%2,%3}, {%4,%5,%6,%7}, {%8,%9}, {%0,%1,%2,%3};"      \
                 : "+f"((c)[0]), "+f"((c)[1]), "+f"((c)[2]), "+f"((c)[3])     \
                 : "r"(a0), "r"(a1), "r"(a2), "r"(a3), "r"(b0), "r"(b1))

// FMA-pipe exp(x): rint via magic constant; 2^f deg-5 poly (abs err ~2.4e-6).
__device__ __forceinline__ float fexp(float x) {
    x = fmaxf(x, -60.0f);
    float y = x * 1.4426950408889634f;
    float km = y + 12582912.0f;
    int   n  = __float_as_int(km) - 0x4B400000;
    float f  = y - (km - 12582912.0f);
    float p = 1.3333558e-3f;
    p = fmaf(p, f, 9.6181291e-3f);
    p = fmaf(p, f, 5.5504109e-2f);
    p = fmaf(p, f, 2.4022651e-1f);
    p = fmaf(p, f, 6.9314718e-1f);
    p = fmaf(p, f, 1.0f);
    return __int_as_float(__float_as_int(p) + (n << 23));
}

// ---------------------------------------------------------------------------
// fp16 GEMM: C[M,N] = alpha*A[M,K]@B[N,K]^T (+bias), f32 acc.
// CTA tile 128x128, 8 warps (warp tile 64x32), BK=64 halves, 3-stage cp.async.
// MODE 0: plain store (OUT_HALF: half2 vs float2).
// MODE 2: fused k|v — n0<512: k store; n0>=512: vT via smem staging (bias2).
// MODE 3: scores — store exp(acc*alpha - 8) as half (softmax numerator).
// MODE 4: attn-v — scale rows by bias2[global row] (1/rowsum), half store.
// ---------------------------------------------------------------------------
template <int MODE, int OUT_HALF>
__global__ __launch_bounds__(256, 2)
void h16_mma_gemm(const __half* __restrict__ A, const __half* __restrict__ Bm,
                  const float* __restrict__ bias, const float* __restrict__ bias2,
                  void* __restrict__ Cv, __half* __restrict__ C2,
                  int N, int K,
                  long long sA, long long sB, long long sC, float alpha)
{
    extern __shared__ char smem[];
    const uint32_t sb = smem_u32(smem);
    const int tid = threadIdx.x;
    const int wid = tid >> 5, lane = tid & 31;
    const int warp_m = wid & 1;
    const int warp_n = wid >> 1;

    A  += (long long)blockIdx.z * sA;
    Bm += (long long)blockIdx.z * sB;
    const int m0 = blockIdx.y * 128;
    const int n0 = blockIdx.x * 128;
    const int KT = (K + 63) >> 6;

    auto load_stage = [&](int kt, int s) {
        const int k0 = kt << 6;
        const uint32_t base = sb + (uint32_t)s * 32768u;
#pragma unroll
        for (int i = 0; i < 4; i++) {
            int e = tid + (i << 8);
            int row = e >> 3, c = e & 7;
            int kk = k0 + (c << 3);
            uint32_t off = (uint32_t)(row * 128) + (uint32_t)((c ^ (row & 7)) << 4);
            const bool kin = kk < K;
            const __half* ga = A + (long long)(m0 + row) * K + kk;
            cp16(base + off, ga, kin ? 16 : 0);
            const bool bin = kin && (n0 + row) < N;
            const __half* gb = Bm + (long long)(n0 + row) * K + kk;
            cp16(base + 16384u + off, bin ? gb : Bm, bin ? 16 : 0);
        }
        asm volatile("cp.async.commit_group;" ::: "memory");
    };

    float acc[4][4][4];
#pragma unroll
    for (int i = 0; i < 4; i++)
#pragma unroll
        for (int j = 0; j < 4; j++)
#pragma unroll
            for (int k = 0; k < 4; k++) acc[i][j][k] = 0.f;

    const int t = lane >> 3, r = lane & 7;
    const uint32_t a_row = (uint32_t)(warp_m * 64 + (t & 1) * 8 + r);
    const uint32_t b_row = (uint32_t)(warp_n * 32 + (t & 1) * 8 + r);
    const uint32_t chb   = (uint32_t)(t >> 1);

    load_stage(0, 0);
    if (KT > 1) load_stage(1, 1);

    for (int kt = 0; kt < KT; kt++) {
        if (kt + 1 < KT) asm volatile("cp.async.wait_group 1;" ::: "memory");
        else             asm volatile("cp.async.wait_group 0;" ::: "memory");
        __syncthreads();
        if (kt + 2 < KT) load_stage(kt + 2, (kt + 2) % 3);

        const uint32_t baseA = sb + (uint32_t)(kt % 3) * 32768u;
        const uint32_t baseB = baseA + 16384u;

#pragma unroll
        for (int ks = 0; ks < 4; ks++) {
            uint32_t a[4][4], b[2][4];
#pragma unroll
            for (int mi = 0; mi < 4; mi++) {
                uint32_t addr = baseA + (a_row + mi * 16) * 128u
                              + ((((ks * 2) + chb) ^ (uint32_t)r) << 4);
                LDSM_X4(a[mi][0], a[mi][1], a[mi][2], a[mi][3], addr);
            }
#pragma unroll
            for (int j = 0; j < 2; j++) {
                uint32_t addr = baseB + (b_row + j * 16) * 128u
                              + ((((ks * 2) + chb) ^ (uint32_t)r) << 4);
                LDSM_X4(b[j][0], b[j][1], b[j][2], b[j][3], addr);
            }
#pragma unroll
            for (int mi = 0; mi < 4; mi++)
#pragma unroll
                for (int ni = 0; ni < 4; ni++)
                    MMA_F16(acc[mi][ni], a[mi][0], a[mi][1], a[mi][2], a[mi][3],
                            b[ni >> 1][ni & 1], b[ni >> 1][(ni & 1) + 2]);
        }
    }

    const int m_base_l = warp_m * 64;
    const int n_base_l = warp_n * 32;
    const int row_in = lane >> 2;
    const int col_in = (lane & 3) * 2;

    if (MODE == 3) {
        // softmax numerator: exp(alpha*s - 8), half store
        __half* C = (__half*)Cv + (long long)blockIdx.z * sC;
#pragma unroll
        for (int mi = 0; mi < 4; mi++) {
            const int gm0 = m0 + m_base_l + mi * 16 + row_in;
#pragma unroll
            for (int ni = 0; ni < 4; ni++) {
                const int gn = n0 + n_base_l + ni * 8 + col_in;
                float v00 = fexp(fmaf(acc[mi][ni][0], alpha, -8.f));
                float v01 = fexp(fmaf(acc[mi][ni][1], alpha, -8.f));
                float v10 = fexp(fmaf(acc[mi][ni][2], alpha, -8.f));
                float v11 = fexp(fmaf(acc[mi][ni][3], alpha, -8.f));
                *reinterpret_cast<__half2*>(&C[(long long)gm0 * N + gn]) =
                    __floats2half2_rn(v00, v01);
                *reinterpret_cast<__half2*>(&C[(long long)(gm0 + 8) * N + gn]) =
                    __floats2half2_rn(v10, v11);
            }
        }
    } else if (MODE == 4) {
        // attn-v: scale by 1/rowsum (bias2 indexed by global row), half store
        __half* C = (__half*)Cv + (long long)blockIdx.z * sC;
        const float* rsc = bias2 + (long long)blockIdx.z * SR_;
#pragma unroll
        for (int mi = 0; mi < 4; mi++) {
            const int gm0 = m0 + m_base_l + mi * 16 + row_in;
            const float s0 = __ldg(&rsc[gm0]);
            const float s1 = __ldg(&rsc[gm0 + 8]);
#pragma unroll
            for (int ni = 0; ni < 4; ni++) {
                const int gn = n0 + n_base_l + ni * 8 + col_in;
                *reinterpret_cast<__half2*>(&C[(long long)gm0 * N + gn]) =
                    __floats2half2_rn(acc[mi][ni][0] * s0, acc[mi][ni][1] * s0);
                *reinterpret_cast<__half2*>(&C[(long long)(gm0 + 8) * N + gn]) =
                    __floats2half2_rn(acc[mi][ni][2] * s1, acc[mi][ni][3] * s1);
            }
        }
    } else if (MODE == 0 || (MODE == 2 && n0 < 512)) {
        const int ldC = (MODE == 2) ? 512 : N;
#pragma unroll
        for (int mi = 0; mi < 4; mi++) {
            const int gm0 = m0 + m_base_l + mi * 16 + row_in;
#pragma unroll
            for (int ni = 0; ni < 4; ni++) {
                const int gn = n0 + n_base_l + ni * 8 + col_in;
                if (gn < N) {
                    float b0 = bias ? __ldg(&bias[gn]) : 0.f;
                    float b1 = bias ? __ldg(&bias[gn + 1]) : 0.f;
                    float v00 = acc[mi][ni][0] * alpha + b0;
                    float v01 = acc[mi][ni][1] * alpha + b1;
                    float v10 = acc[mi][ni][2] * alpha + b0;
                    float v11 = acc[mi][ni][3] * alpha + b1;
                    if (OUT_HALF) {
                        __half* C = (__half*)Cv + (long long)blockIdx.z * sC;
                        *reinterpret_cast<__half2*>(&C[(long long)gm0 * ldC + gn]) =
                            __floats2half2_rn(v00, v01);
                        *reinterpret_cast<__half2*>(&C[(long long)(gm0 + 8) * ldC + gn]) =
                            __floats2half2_rn(v10, v11);
                    } else {
                        float* C = (float*)Cv + (long long)blockIdx.z * sC;
                        *reinterpret_cast<float2*>(&C[(long long)gm0 * ldC + gn]) =
                            make_float2(v00, v01);
                        *reinterpret_cast<float2*>(&C[(long long)(gm0 + 8) * ldC + gn]) =
                            make_float2(v10, v11);
                    }
                }
            }
        }
    } else {
        // v side of MODE 2: vT[b][h][p], h = gn - 512. Stage [n][m] in smem.
        __syncthreads();
        __half* sm = reinterpret_cast<__half*>(smem);
        const int PAD = 136;
        const int h0 = n0 - 512;
#pragma unroll
        for (int mi = 0; mi < 4; mi++) {
            const int ml = m_base_l + mi * 16 + row_in;
#pragma unroll
            for (int ni = 0; ni < 4; ni++) {
                const int nl = n_base_l + ni * 8 + col_in;
                float b0 = bias2 ? __ldg(&bias2[h0 + nl]) : 0.f;
                float b1 = bias2 ? __ldg(&bias2[h0 + nl + 1]) : 0.f;
                sm[nl * PAD + ml]           = __float2half_rn(acc[mi][ni][0] + b0);
                sm[(nl + 1) * PAD + ml]     = __float2half_rn(acc[mi][ni][1] + b1);
                sm[nl * PAD + ml + 8]       = __float2half_rn(acc[mi][ni][2] + b0);
                sm[(nl + 1) * PAD + ml + 8] = __float2half_rn(acc[mi][ni][3] + b1);
            }
        }
        __syncthreads();
        const long long obase = ((long long)(m0 >> 11) << 20) + (m0 & 2047);
#pragma unroll
        for (int pass = 0; pass < 8; pass++) {
            int chunk = pass * 256 + tid;
            int n = chunk >> 4;
            int mc = (chunk & 15) << 3;
            uint4 v = *reinterpret_cast<uint4*>(&sm[n * PAD + mc]);
            *reinterpret_cast<uint4*>(&C2[obase + ((long long)(h0 + n) << 11) + mc]) = v;
        }
    }
}

// ---------------------------------------------------------------------------
// rgb & pose -> half copies
// ---------------------------------------------------------------------------
__global__ __launch_bounds__(256)
void prep_half(const float* __restrict__ rgb, const float* __restrict__ pose,
               __half* __restrict__ rgbh, __half* __restrict__ poseh)
{
    const long long NEL4 = (long long)MROWS * DIM_ / 4;
    long long idx = (long long)blockIdx.x * 256 + threadIdx.x;
    const float* src; __half* dst; long long j;
    if (idx < NEL4)          { src = rgb;  dst = rgbh;  j = idx; }
    else if (idx < 2 * NEL4) { src = pose; dst = poseh; j = idx - NEL4; }
    else return;
    float4 v = reinterpret_cast<const float4*>(src)[j];
    __half2 h0 = __floats2half2_rn(v.x, v.y);
    __half2 h1 = __floats2half2_rn(v.z, v.w);
    reinterpret_cast<uint2*>(dst)[j] = make_uint2(
        *reinterpret_cast<uint32_t*>(&h0), *reinterpret_cast<uint32_t*>(&h1));
}

// ---------------------------------------------------------------------------
// Weight transpose -> half: WqT/WkT/WvT [512,400]; WpT [400,512]
// ---------------------------------------------------------------------------
__global__ __launch_bounds__(256)
void transpose_w(const float* __restrict__ Wq, const float* __restrict__ Wk,
                 const float* __restrict__ Wv, const float* __restrict__ Wp,
                 __half* __restrict__ out)
{
    const int SZ = 512 * 400;
    int idx = blockIdx.x * 256 + threadIdx.x;
    if (idx < 3 * SZ) {
        int w = idx / SZ, rr = idx % SZ;
        int h = rr / 400, dd = rr % 400;
        const float* W = (w == 0) ? Wq : (w == 1) ? Wk : Wv;
        out[idx] = __float2half_rn(W[dd * 512 + h]);
    } else if (idx < 4 * SZ) {
        int rr = idx - 3 * SZ;
        int n = rr / 512, kk = rr % 512;
        out[idx] = __float2half_rn(Wp[kk * 400 + n]);
    }
}

// ---------------------------------------------------------------------------
// Row sums of unnormalized probs -> inv[row] = 1/sum. One warp per row.
// ---------------------------------------------------------------------------
__global__ __launch_bounds__(256)
void rowsum_kernel(const __half* __restrict__ P, float* __restrict__ inv)
{
    const int row = blockIdx.x * 8 + (threadIdx.x >> 5);
    const int lane = threadIdx.x & 31;
    const uint4* rp = reinterpret_cast<const uint4*>(P + (long long)row * SP_);
    float s = 0.f;
#pragma unroll
    for (int i = 0; i < 8; i++) {            // 8 uint4 x 32 lanes = 2048 halves
        uint4 w = rp[lane + i * 32];
        const __half2* h = reinterpret_cast<const __half2*>(&w);
#pragma unroll
        for (int j = 0; j < 4; j++) {
            float2 f = __half22float2(h[j]);
            s += f.x + f.y;
        }
    }
#pragma unroll
    for (int d = 16; d > 0; d >>= 1)
        s += __shfl_xor_sync(0xFFFFFFFFu, s, d);
    if (lane == 0) inv[row] = 1.f / s;
}

// ---------------------------------------------------------------------------
// x = rgb + gate*proj ; out = LN(x)*gamma + beta
// ---------------------------------------------------------------------------
__global__ __launch_bounds__(256)
void residual_ln_kernel(const float* __restrict__ proj, const float* __restrict__ rgb,
                        const float* __restrict__ gamma, const float* __restrict__ beta,
                        const float* __restrict__ gate, float* __restrict__ out)
{
    const long long row = blockIdx.x;
    const float g = gate[0];
    const float* pr = proj + row * DIM_;
    const float* rr = rgb + row * DIM_;
    float* orow = out + row * DIM_;
    const int tid = threadIdx.x;
    const int i1 = tid + 256;
    const bool has1 = (i1 < DIM_);

    float x0 = rr[tid] + g * pr[tid];
    float x1 = has1 ? (rr[i1] + g * pr[i1]) : 0.f;

    __shared__ float rs[256], rs2[256];
    rs[tid] = x0 + x1;
    rs2[tid] = x0 * x0 + x1 * x1;
    __syncthreads();
#pragma unroll
    for (int s = 128; s > 0; s >>= 1) {
        if (tid < s) { rs[tid] += rs[tid + s]; rs2[tid] += rs2[tid + s]; }
        __syncthreads();
    }
    const float mean = rs[0] * (1.f / DIM_);
    const float var  = rs2[0] * (1.f / DIM_) - mean * mean;
    const float inv  = rsqrtf(var + 1e-5f);

    orow[tid] = (x0 - mean) * inv * gamma[tid] + beta[tid];
    if (has1) orow[i1] = (x1 - mean) * inv * gamma[i1] + beta[i1];
}

// ---------------------------------------------------------------------------
// Launch
// ---------------------------------------------------------------------------
extern "C" void kernel_launch(void* const* d_in, const int* in_sizes, int n_in,
                              void* d_out, int out_size)
{
    const float* rgb  = (const float*)d_in[0];
    const float* pose = (const float*)d_in[1];
    const float* Wq   = (const float*)d_in[2];
    const float* bq   = (const float*)d_in[3];
    const float* Wk   = (const float*)d_in[4];
    const float* bk   = (const float*)d_in[5];
    const float* Wv   = (const float*)d_in[6];
    const float* bv   = (const float*)d_in[7];
    const float* Wp   = (const float*)d_in[8];
    const float* bp   = (const float*)d_in[9];
    const float* lng  = (const float*)d_in[10];
    const float* lnb  = (const float*)d_in[11];
    const float* gate = (const float*)d_in[12];
    float* out = (float*)d_out;

    __half *q, *k, *vt, *pu, *o, *wt, *rgbh, *poseh;
    float *p, *inv;
    cudaGetSymbolAddress((void**)&q,  g_q);
    cudaGetSymbolAddress((void**)&k,  g_k);
    cudaGetSymbolAddress((void**)&vt, g_vt);
    cudaGetSymbolAddress((void**)&pu, g_pu);
    cudaGetSymbolAddress((void**)&inv, g_inv);
    cudaGetSymbolAddress((void**)&o,  g_o);
    cudaGetSymbolAddress((void**)&p,  g_p);
    cudaGetSymbolAddress((void**)&wt, g_wt);
    cudaGetSymbolAddress((void**)&rgbh,  g_rgbh);
    cudaGetSymbolAddress((void**)&poseh, g_poseh);

    const int SMEM = 3 * 32768;        // 96 KB
    cudaFuncSetAttribute(h16_mma_gemm<0,1>, cudaFuncAttributeMaxDynamicSharedMemorySize, SMEM);
    cudaFuncSetAttribute(h16_mma_gemm<0,0>, cudaFuncAttributeMaxDynamicSharedMemorySize, SMEM);
    cudaFuncSetAttribute(h16_mma_gemm<2,1>, cudaFuncAttributeMaxDynamicSharedMemorySize, SMEM);
    cudaFuncSetAttribute(h16_mma_gemm<3,1>, cudaFuncAttributeMaxDynamicSharedMemorySize, SMEM);
    cudaFuncSetAttribute(h16_mma_gemm<4,1>, cudaFuncAttributeMaxDynamicSharedMemorySize, SMEM);

    const int WSZ = 512 * 400;

    // 0. prep
    {
        long long n4 = 2LL * MROWS * DIM_ / 4;
        prep_half<<<(unsigned)((n4 + 255) / 256), 256>>>(rgb, pose, rgbh, poseh);
        transpose_w<<<(4 * WSZ + 255) / 256, 256>>>(Wq, Wk, Wv, Wp, wt);
    }

    // 1. q projection -> half
    {
        dim3 grid(4, MROWS / 128, 1);
        h16_mma_gemm<0,1><<<grid, 256, SMEM>>>(
            rgbh, wt, bq, nullptr, q, nullptr, HID_, DIM_, 0, 0, 0, 1.f);
    }
    // 2. fused k|v projection: B = [WkT;WvT] (1024x400); k plain, v -> vT
    {
        dim3 grid(8, MROWS / 128, 1);
        h16_mma_gemm<2,1><<<grid, 256, SMEM>>>(
            poseh, wt + WSZ, bk, bv, k, vt, 1024, DIM_, 0, 0, 0, 1.f);
    }
    // 3. probs_unnorm = exp(q@k^T/sqrt(512) - 8) -> half, batched
    {
        dim3 grid(SP_ / 128, SR_ / 128, B_);
        h16_mma_gemm<3,1><<<grid, 256, SMEM>>>(
            q, k, nullptr, nullptr, pu, nullptr, SP_, HID_,
            (long long)SR_ * HID_, (long long)SP_ * HID_,
            (long long)SR_ * SP_, 0.044194173824159216f);
    }
    // 4. row sums -> inv
    rowsum_kernel<<<MROWS / 8, 256>>>(pu, inv);

    // 5. O = (probs_unnorm @ v) * inv[row] -> half, batched
    {
        dim3 grid(HID_ / 128, SR_ / 128, B_);
        h16_mma_gemm<4,1><<<grid, 256, SMEM>>>(
            pu, vt, nullptr, inv, o, nullptr, HID_, SP_,
            (long long)SR_ * SP_, (long long)HID_ * SP_,
            (long long)SR_ * HID_, 1.f);
    }
    // 6. proj = O @ Wp + bp -> fp32
    {
        dim3 grid((DIM_ + 127) / 128, MROWS / 128, 1);
        h16_mma_gemm<0,0><<<grid, 256, SMEM>>>(
            o, wt + 3 * WSZ, bp, nullptr, p, nullptr, DIM_, HID_, 0, 0, 0, 1.f);
    }
    // 7. residual + LayerNorm
    residual_ln_kernel<<<MROWS, 256>>>(p, rgb, lng, lnb, gate, out);
}

// round 12
// speedup vs baseline: 1.0465x; 1.0217x over previous
#include <cuda_runtime.h>
#include <cuda_fp16.h>
#include <cstdint>
#include <math.h>

// ---------------------------------------------------------------------------
// CrossModalFusion, fp16 mma.sync (m16n8k16, f32 acc).
// R12: merged q|k|v projection kernel; rowsum fused into scores epilogue.
// B=32, Sr=Sp=2048, D=400, H=512
// ---------------------------------------------------------------------------
#define B_   32
#define SR_  2048
#define SP_  2048
#define DIM_ 400
#define HID_ 512
#define MROWS (B_ * SR_)          // 65536

__device__ __half g_q [(size_t)MROWS * HID_];
__device__ __half g_k [(size_t)MROWS * HID_];
__device__ __half g_vt[(size_t)MROWS * HID_];     // [B][H][Sp]
__device__ __half g_pu[(size_t)B_ * SR_ * SP_];   // unnormalized probs (half)
__device__ float  g_rs[(size_t)MROWS * 64];       // per-row partial sums (16MB)
__device__ float  g_inv[(size_t)MROWS];           // 1/rowsum
__device__ __half g_o [(size_t)MROWS * HID_];
__device__ float  g_p [(size_t)MROWS * DIM_];
__device__ __half g_wt[4 * 512 * 400];            // WqT | WkT | WvT | WpT
__device__ __half g_rgbh [(size_t)MROWS * DIM_];
__device__ __half g_poseh[(size_t)MROWS * DIM_];

__device__ __forceinline__ uint32_t smem_u32(const void* p) {
    uint32_t a;
    asm("{ .reg .u64 t; cvta.to.shared.u64 t, %1; cvt.u32.u64 %0, t; }" : "=r"(a) : "l"(p));
    return a;
}
__device__ __forceinline__ void cp16(uint32_t dst, const void* src, int bytes) {
    asm volatile("cp.async.cg.shared.global [%0], [%1], 16, %2;"
                 :: "r"(dst), "l"(src), "r"(bytes));
}
#define LDSM_X4(r0, r1, r2, r3, addr)                                         \
    asm volatile("ldmatrix.sync.aligned.m8n8.x4.shared.b16 {%0,%1,%2,%3}, [%4];" \
                 : "=r"(r0), "=r"(r1), "=r"(r2), "=r"(r3) : "r"(addr))

#define MMA_F16(c, a0, a1, a2, a3, b0, b1)                                    \
    asm volatile("mma.sync.aligned.m16n8k16.row.col.f32.f16.f16.f32 "         \
                 "{%0,%1,%2,%3}, {%4,%5,%6,%7}, {%8,%9}, {%0,%1,%2,%3};"      \
                 : "+f"((c)[0]), "+f"((c)[1]), "+f"((c)[2]), "+f"((c)[3])     \
                 : "r"(a0), "r"(a1), "r"(a2), "r"(a3), "r"(b0), "r"(b1))

// FMA-pipe exp(x): rint via magic constant; 2^f deg-5 poly (abs err ~2.4e-6).
__device__ __forceinline__ float fexp(float x) {
    x = fmaxf(x, -60.0f);
    float y = x * 1.4426950408889634f;
    float km = y + 12582912.0f;
    int   n  = __float_as_int(km) - 0x4B400000;
    float f  = y - (km - 12582912.0f);
    float p = 1.3333558e-3f;
    p = fmaf(p, f, 9.6181291e-3f);
    p = fmaf(p, f, 5.5504109e-2f);
    p = fmaf(p, f, 2.4022651e-1f);
    p = fmaf(p, f, 6.9314718e-1f);
    p = fmaf(p, f, 1.0f);
    return __int_as_float(__float_as_int(p) + (n << 23));
}

// ---------------------------------------------------------------------------
// fp16 GEMM: C = alpha*A@B^T (+bias), f32 acc. CTA tile 128x128, 8 warps
// (warp tile 64x32), BK=64 halves, 3-stage cp.async.
// MODE 0: plain store (OUT_HALF picks type).
// MODE 3: scores — store exp(acc*alpha - 8) half + per-row partial sums -> C3.
// MODE 4: attn-v — scale rows by bias2[global row], half store.
// MODE 5: merged q|k|v — bx<4: q (A2,Bm2,bias3->C3); bx in 4..7: k (bias->Cv);
//         bx in 8..11: vT via smem staging (bias2->C2).
// ---------------------------------------------------------------------------
template <int MODE, int OUT_HALF>
__global__ __launch_bounds__(256, 2)
void h16_mma_gemm(const __half* __restrict__ A, const __half* __restrict__ Bm,
                  const float* __restrict__ bias, const float* __restrict__ bias2,
                  void* __restrict__ Cv, __half* __restrict__ C2,
                  int N, int K,
                  long long sA, long long sB, long long sC, float alpha,
                  const __half* __restrict__ A2, const __half* __restrict__ Bm2,
                  const float* __restrict__ bias3, void* __restrict__ C3)
{
    extern __shared__ char smem[];
    const uint32_t sb = smem_u32(smem);
    const int tid = threadIdx.x;
    const int wid = tid >> 5, lane = tid & 31;
    const int warp_m = wid & 1;
    const int warp_n = wid >> 1;
    const int bx = blockIdx.x;

    const __half* Ap = A;
    const __half* Bp = Bm;
    int n0;
    if (MODE == 5) {
        if (bx < 4) { Ap = A2; Bp = Bm2; n0 = bx * 128; }
        else        { n0 = (bx - 4) * 128; }
    } else {
        n0 = bx * 128;
    }
    Ap += (long long)blockIdx.z * sA;
    Bp += (long long)blockIdx.z * sB;
    const int m0 = blockIdx.y * 128;
    const int KT = (K + 63) >> 6;

    auto load_stage = [&](int kt, int s) {
        const int k0 = kt << 6;
        const uint32_t base = sb + (uint32_t)s * 32768u;
#pragma unroll
        for (int i = 0; i < 4; i++) {
            int e = tid + (i << 8);
            int row = e >> 3, c = e & 7;
            int kk = k0 + (c << 3);
            uint32_t off = (uint32_t)(row * 128) + (uint32_t)((c ^ (row & 7)) << 4);
            const bool kin = kk < K;
            const __half* ga = Ap + (long long)(m0 + row) * K + kk;
            cp16(base + off, ga, kin ? 16 : 0);
            const bool bin = kin && (n0 + row) < N;
            const __half* gb = Bp + (long long)(n0 + row) * K + kk;
            cp16(base + 16384u + off, bin ? gb : Bp, bin ? 16 : 0);
        }
        asm volatile("cp.async.commit_group;" ::: "memory");
    };

    float acc[4][4][4];
#pragma unroll
    for (int i = 0; i < 4; i++)
#pragma unroll
        for (int j = 0; j < 4; j++)
#pragma unroll
            for (int k = 0; k < 4; k++) acc[i][j][k] = 0.f;

    const int t = lane >> 3, r = lane & 7;
    const uint32_t a_row = (uint32_t)(warp_m * 64 + (t & 1) * 8 + r);
    const uint32_t b_row = (uint32_t)(warp_n * 32 + (t & 1) * 8 + r);
    const uint32_t chb   = (uint32_t)(t >> 1);

    load_stage(0, 0);
    if (KT > 1) load_stage(1, 1);

    for (int kt = 0; kt < KT; kt++) {
        if (kt + 1 < KT) asm volatile("cp.async.wait_group 1;" ::: "memory");
        else             asm volatile("cp.async.wait_group 0;" ::: "memory");
        __syncthreads();
        if (kt + 2 < KT) load_stage(kt + 2, (kt + 2) % 3);

        const uint32_t baseA = sb + (uint32_t)(kt % 3) * 32768u;
        const uint32_t baseB = baseA + 16384u;

#pragma unroll
        for (int ks = 0; ks < 4; ks++) {
            uint32_t a[4][4], b[2][4];
#pragma unroll
            for (int mi = 0; mi < 4; mi++) {
                uint32_t addr = baseA + (a_row + mi * 16) * 128u
                              + ((((ks * 2) + chb) ^ (uint32_t)r) << 4);
                LDSM_X4(a[mi][0], a[mi][1], a[mi][2], a[mi][3], addr);
            }
#pragma unroll
            for (int j = 0; j < 2; j++) {
                uint32_t addr = baseB + (b_row + j * 16) * 128u
                              + ((((ks * 2) + chb) ^ (uint32_t)r) << 4);
                LDSM_X4(b[j][0], b[j][1], b[j][2], b[j][3], addr);
            }
#pragma unroll
            for (int mi = 0; mi < 4; mi++)
#pragma unroll
                for (int ni = 0; ni < 4; ni++)
                    MMA_F16(acc[mi][ni], a[mi][0], a[mi][1], a[mi][2], a[mi][3],
                            b[ni >> 1][ni & 1], b[ni >> 1][(ni & 1) + 2]);
        }
    }

    const int m_base_l = warp_m * 64;
    const int n_base_l = warp_n * 32;
    const int row_in = lane >> 2;
    const int col_in = (lane & 3) * 2;

    if (MODE == 3) {
        // softmax numerator: exp(alpha*s - 8), half store + partial row sums
        __half* C = (__half*)Cv + (long long)blockIdx.z * sC;
        float* rs = (float*)C3;
        const long long growb = (long long)blockIdx.z * SR_;
        const int cb = (n0 >> 5) + warp_n;     // 0..63 column block
#pragma unroll
        for (int mi = 0; mi < 4; mi++) {
            const int gm0 = m0 + m_base_l + mi * 16 + row_in;
            float s0 = 0.f, s1 = 0.f;
#pragma unroll
            for (int ni = 0; ni < 4; ni++) {
                const int gn = n0 + n_base_l + ni * 8 + col_in;
                float v00 = fexp(fmaf(acc[mi][ni][0], alpha, -8.f));
                float v01 = fexp(fmaf(acc[mi][ni][1], alpha, -8.f));
                float v10 = fexp(fmaf(acc[mi][ni][2], alpha, -8.f));
                float v11 = fexp(fmaf(acc[mi][ni][3], alpha, -8.f));
                s0 += v00 + v01;
                s1 += v10 + v11;
                *reinterpret_cast<__half2*>(&C[(long long)gm0 * N + gn]) =
                    __floats2half2_rn(v00, v01);
                *reinterpret_cast<__half2*>(&C[(long long)(gm0 + 8) * N + gn]) =
                    __floats2half2_rn(v10, v11);
            }
            // reduce over the 4 lanes covering this row (lane&3)
            s0 += __shfl_xor_sync(0xFFFFFFFFu, s0, 1);
            s0 += __shfl_xor_sync(0xFFFFFFFFu, s0, 2);
            s1 += __shfl_xor_sync(0xFFFFFFFFu, s1, 1);
            s1 += __shfl_xor_sync(0xFFFFFFFFu, s1, 2);
            if ((lane & 3) == 0) {
                rs[(growb + gm0) * 64 + cb]     = s0;
                rs[(growb + gm0 + 8) * 64 + cb] = s1;
            }
        }
    } else if (MODE == 4) {
        // attn-v: scale by 1/rowsum (bias2 indexed by global row), half store
        __half* C = (__half*)Cv + (long long)blockIdx.z * sC;
        const float* rsc = bias2 + (long long)blockIdx.z * SR_;
#pragma unroll
        for (int mi = 0; mi < 4; mi++) {
            const int gm0 = m0 + m_base_l + mi * 16 + row_in;
            const float s0 = __ldg(&rsc[gm0]);
            const float s1 = __ldg(&rsc[gm0 + 8]);
#pragma unroll
            for (int ni = 0; ni < 4; ni++) {
                const int gn = n0 + n_base_l + ni * 8 + col_in;
                *reinterpret_cast<__half2*>(&C[(long long)gm0 * N + gn]) =
                    __floats2half2_rn(acc[mi][ni][0] * s0, acc[mi][ni][1] * s0);
                *reinterpret_cast<__half2*>(&C[(long long)(gm0 + 8) * N + gn]) =
                    __floats2half2_rn(acc[mi][ni][2] * s1, acc[mi][ni][3] * s1);
            }
        }
    } else if (MODE == 0 || (MODE == 5 && bx < 8)) {
        // plain store; MODE5: q side (bx<4) -> C3/bias3, k side -> Cv/bias
        const bool qs = (MODE == 5) && (bx < 4);
        const int ldC = (MODE == 5) ? 512 : N;
        const float* bb = qs ? bias3 : bias;
#pragma unroll
        for (int mi = 0; mi < 4; mi++) {
            const int gm0 = m0 + m_base_l + mi * 16 + row_in;
#pragma unroll
            for (int ni = 0; ni < 4; ni++) {
                const int gn = n0 + n_base_l + ni * 8 + col_in;
                if (gn < N) {
                    float b0 = bb ? __ldg(&bb[gn]) : 0.f;
                    float b1 = bb ? __ldg(&bb[gn + 1]) : 0.f;
                    float v00 = acc[mi][ni][0] * alpha + b0;
                    float v01 = acc[mi][ni][1] * alpha + b1;
                    float v10 = acc[mi][ni][2] * alpha + b0;
                    float v11 = acc[mi][ni][3] * alpha + b1;
                    if (OUT_HALF) {
                        __half* C = qs ? (__half*)C3
                                       : (__half*)Cv + (long long)blockIdx.z * sC;
                        *reinterpret_cast<__half2*>(&C[(long long)gm0 * ldC + gn]) =
                            __floats2half2_rn(v00, v01);
                        *reinterpret_cast<__half2*>(&C[(long long)(gm0 + 8) * ldC + gn]) =
                            __floats2half2_rn(v10, v11);
                    } else {
                        float* C = (float*)Cv + (long long)blockIdx.z * sC;
                        *reinterpret_cast<float2*>(&C[(long long)gm0 * ldC + gn]) =
                            make_float2(v00, v01);
                        *reinterpret_cast<float2*>(&C[(long long)(gm0 + 8) * ldC + gn]) =
                            make_float2(v10, v11);
                    }
                }
            }
        }
    } else {
        // MODE5 v side: vT[b][h][p], h = gn - 512. Stage [n][m] in smem.
        __syncthreads();
        __half* sm = reinterpret_cast<__half*>(smem);
        const int PAD = 136;
        const int h0 = n0 - 512;
#pragma unroll
        for (int mi = 0; mi < 4; mi++) {
            const int ml = m_base_l + mi * 16 + row_in;
#pragma unroll
            for (int ni = 0; ni < 4; ni++) {
                const int nl = n_base_l + ni * 8 + col_in;
                float b0 = bias2 ? __ldg(&bias2[h0 + nl]) : 0.f;
                float b1 = bias2 ? __ldg(&bias2[h0 + nl + 1]) : 0.f;
                sm[nl * PAD + ml]           = __float2half_rn(acc[mi][ni][0] + b0);
                sm[(nl + 1) * PAD + ml]     = __float2half_rn(acc[mi][ni][1] + b1);
                sm[nl * PAD + ml + 8]       = __float2half_rn(acc[mi][ni][2] + b0);
                sm[(nl + 1) * PAD + ml + 8] = __float2half_rn(acc[mi][ni][3] + b1);
            }
        }
        __syncthreads();
        const long long obase = ((long long)(m0 >> 11) << 20) + (m0 & 2047);
#pragma unroll
        for (int pass = 0; pass < 8; pass++) {
            int chunk = pass * 256 + tid;
            int n = chunk >> 4;
            int mc = (chunk & 15) << 3;
            uint4 v = *reinterpret_cast<uint4*>(&sm[n * PAD + mc]);
            *reinterpret_cast<uint4*>(&C2[obase + ((long long)(h0 + n) << 11) + mc]) = v;
        }
    }
}

// ---------------------------------------------------------------------------
// rgb & pose -> half copies
// ---------------------------------------------------------------------------
__global__ __launch_bounds__(256)
void prep_half(const float* __restrict__ rgb, const float* __restrict__ pose,
               __half* __restrict__ rgbh, __half* __restrict__ poseh)
{
    const long long NEL4 = (long long)MROWS * DIM_ / 4;
    long long idx = (long long)blockIdx.x * 256 + threadIdx.x;
    const float* src; __half* dst; long long j;
    if (idx < NEL4)          { src = rgb;  dst = rgbh;  j = idx; }
    else if (idx < 2 * NEL4) { src = pose; dst = poseh; j = idx - NEL4; }
    else return;
    float4 v = reinterpret_cast<const float4*>(src)[j];
    __half2 h0 = __floats2half2_rn(v.x, v.y);
    __half2 h1 = __floats2half2_rn(v.z, v.w);
    reinterpret_cast<uint2*>(dst)[j] = make_uint2(
        *reinterpret_cast<uint32_t*>(&h0), *reinterpret_cast<uint32_t*>(&h1));
}

// ---------------------------------------------------------------------------
// Weight transpose -> half: WqT/WkT/WvT [512,400]; WpT [400,512]
// ---------------------------------------------------------------------------
__global__ __launch_bounds__(256)
void transpose_w(const float* __restrict__ Wq, const float* __restrict__ Wk,
                 const float* __restrict__ Wv, const float* __restrict__ Wp,
                 __half* __restrict__ out)
{
    const int SZ = 512 * 400;
    int idx = blockIdx.x * 256 + threadIdx.x;
    if (idx < 3 * SZ) {
        int w = idx / SZ, rr = idx % SZ;
        int h = rr / 400, dd = rr % 400;
        const float* W = (w == 0) ? Wq : (w == 1) ? Wk : Wv;
        out[idx] = __float2half_rn(W[dd * 512 + h]);
    } else if (idx < 4 * SZ) {
        int rr = idx - 3 * SZ;
        int n = rr / 512, kk = rr % 512;
        out[idx] = __float2half_rn(Wp[kk * 400 + n]);
    }
}

// ---------------------------------------------------------------------------
// inv[row] = 1 / sum(partials[row][0..63]). One warp per row.
// ---------------------------------------------------------------------------
__global__ __launch_bounds__(256)
void inv_kernel(const float* __restrict__ rs, float* __restrict__ inv)
{
    const int row = blockIdx.x * 8 + (threadIdx.x >> 5);
    const int lane = threadIdx.x & 31;
    const float* r = rs + (long long)row * 64;
    float s = r[lane] + r[lane + 32];
#pragma unroll
    for (int d = 16; d > 0; d >>= 1)
        s += __shfl_xor_sync(0xFFFFFFFFu, s, d);
    if (lane == 0) inv[row] = 1.f / s;
}

// ---------------------------------------------------------------------------
// x = rgb + gate*proj ; out = LN(x)*gamma + beta
// ---------------------------------------------------------------------------
__global__ __launch_bounds__(256)
void residual_ln_kernel(const float* __restrict__ proj, const float* __restrict__ rgb,
                        const float* __restrict__ gamma, const float* __restrict__ beta,
                        const float* __restrict__ gate, float* __restrict__ out)
{
    const long long row = blockIdx.x;
    const float g = gate[0];
    const float* pr = proj + row * DIM_;
    const float* rr = rgb + row * DIM_;
    float* orow = out + row * DIM_;
    const int tid = threadIdx.x;
    const int i1 = tid + 256;
    const bool has1 = (i1 < DIM_);

    float x0 = rr[tid] + g * pr[tid];
    float x1 = has1 ? (rr[i1] + g * pr[i1]) : 0.f;

    __shared__ float rs[256], rs2[256];
    rs[tid] = x0 + x1;
    rs2[tid] = x0 * x0 + x1 * x1;
    __syncthreads();
#pragma unroll
    for (int s = 128; s > 0; s >>= 1) {
        if (tid < s) { rs[tid] += rs[tid + s]; rs2[tid] += rs2[tid + s]; }
        __syncthreads();
    }
    const float mean = rs[0] * (1.f / DIM_);
    const float var  = rs2[0] * (1.f / DIM_) - mean * mean;
    const float inv  = rsqrtf(var + 1e-5f);

    orow[tid] = (x0 - mean) * inv * gamma[tid] + beta[tid];
    if (has1) orow[i1] = (x1 - mean) * inv * gamma[i1] + beta[i1];
}

// ---------------------------------------------------------------------------
// Launch
// ---------------------------------------------------------------------------
extern "C" void kernel_launch(void* const* d_in, const int* in_sizes, int n_in,
                              void* d_out, int out_size)
{
    const float* rgb  = (const float*)d_in[0];
    const float* pose = (const float*)d_in[1];
    const float* Wq   = (const float*)d_in[2];
    const float* bq   = (const float*)d_in[3];
    const float* Wk   = (const float*)d_in[4];
    const float* bk   = (const float*)d_in[5];
    const float* Wv   = (const float*)d_in[6];
    const float* bv   = (const float*)d_in[7];
    const float* Wp   = (const float*)d_in[8];
    const float* bp   = (const float*)d_in[9];
    const float* lng  = (const float*)d_in[10];
    const float* lnb  = (const float*)d_in[11];
    const float* gate = (const float*)d_in[12];
    float* out = (float*)d_out;

    __half *q, *k, *vt, *pu, *o, *wt, *rgbh, *poseh;
    float *p, *inv, *rs;
    cudaGetSymbolAddress((void**)&q,  g_q);
    cudaGetSymbolAddress((void**)&k,  g_k);
    cudaGetSymbolAddress((void**)&vt, g_vt);
    cudaGetSymbolAddress((void**)&pu, g_pu);
    cudaGetSymbolAddress((void**)&rs, g_rs);
    cudaGetSymbolAddress((void**)&inv, g_inv);
    cudaGetSymbolAddress((void**)&o,  g_o);
    cudaGetSymbolAddress((void**)&p,  g_p);
    cudaGetSymbolAddress((void**)&wt, g_wt);
    cudaGetSymbolAddress((void**)&rgbh,  g_rgbh);
    cudaGetSymbolAddress((void**)&poseh, g_poseh);

    const int SMEM = 3 * 32768;        // 96 KB
    cudaFuncSetAttribute(h16_mma_gemm<0,0>, cudaFuncAttributeMaxDynamicSharedMemorySize, SMEM);
    cudaFuncSetAttribute(h16_mma_gemm<3,1>, cudaFuncAttributeMaxDynamicSharedMemorySize, SMEM);
    cudaFuncSetAttribute(h16_mma_gemm<4,1>, cudaFuncAttributeMaxDynamicSharedMemorySize, SMEM);
    cudaFuncSetAttribute(h16_mma_gemm<5,1>, cudaFuncAttributeMaxDynamicSharedMemorySize, SMEM);

    const int WSZ = 512 * 400;

    // 0. prep
    {
        long long n4 = 2LL * MROWS * DIM_ / 4;
        prep_half<<<(unsigned)((n4 + 255) / 256), 256>>>(rgb, pose, rgbh, poseh);
        transpose_w<<<(4 * WSZ + 255) / 256, 256>>>(Wq, Wk, Wv, Wp, wt);
    }

    // 1. merged q|k|v projection: bx<4 q (rgbh@WqT), 4..7 k, 8..11 vT (poseh@[WkT;WvT])
    {
        dim3 grid(12, MROWS / 128, 1);
        h16_mma_gemm<5,1><<<grid, 256, SMEM>>>(
            poseh, wt + WSZ, bk, bv, k, vt, 1024, DIM_, 0, 0, 0, 1.f,
            rgbh, wt, bq, q);
    }
    // 2. probs_unnorm = exp(q@k^T/sqrt(512) - 8) -> half + partial row sums
    {
        dim3 grid(SP_ / 128, SR_ / 128, B_);
        h16_mma_gemm<3,1><<<grid, 256, SMEM>>>(
            q, k, nullptr, nullptr, pu, nullptr, SP_, HID_,
            (long long)SR_ * HID_, (long long)SP_ * HID_,
            (long long)SR_ * SP_, 0.044194173824159216f,
            nullptr, nullptr, nullptr, rs);
    }
    // 3. inv = 1/rowsum
    inv_kernel<<<MROWS / 8, 256>>>(rs, inv);

    // 4. O = (probs_unnorm @ v) * inv[row] -> half, batched
    {
        dim3 grid(HID_ / 128, SR_ / 128, B_);
        h16_mma_gemm<4,1><<<grid, 256, SMEM>>>(
            pu, vt, nullptr, inv, o, nullptr, HID_, SP_,
            (long long)SR_ * SP_, (long long)HID_ * SP_,
            (long long)SR_ * HID_, 1.f,
            nullptr, nullptr, nullptr, nullptr);
    }
    // 5. proj = O @ Wp + bp -> fp32
    {
        dim3 grid((DIM_ + 127) / 128, MROWS / 128, 1);
        h16_mma_gemm<0,0><<<grid, 256, SMEM>>>(
            o, wt + 3 * WSZ, bp, nullptr, p, nullptr, DIM_, HID_, 0, 0, 0, 1.f,
            nullptr, nullptr, nullptr, nullptr);
    }
    // 6. residual + LayerNorm
    residual_ln_kernel<<<MROWS, 256>>>(p, rgb, lng, lnb, gate, out);
}

// round 14
// speedup vs baseline: 1.0591x; 1.0120x over previous
#include <cuda_runtime.h>
#include <cuda_fp16.h>
#include <cstdint>
#include <math.h>

// ---------------------------------------------------------------------------
// CrossModalFusion, fp16 mma.sync (m16n8k16, f32 acc).
// R13: all epilogues stage tiles in smem -> fully coalesced 256B row stores.
// B=32, Sr=Sp=2048, D=400, H=512
// ---------------------------------------------------------------------------
#define B_   32
#define SR_  2048
#define SP_  2048
#define DIM_ 400
#define HID_ 512
#define MROWS (B_ * SR_)          // 65536

__device__ __half g_q [(size_t)MROWS * HID_];
__device__ __half g_k [(size_t)MROWS * HID_];
__device__ __half g_vt[(size_t)MROWS * HID_];     // [B][H][Sp]
__device__ __half g_pu[(size_t)B_ * SR_ * SP_];   // unnormalized probs (half)
__device__ float  g_rs[(size_t)MROWS * 64];       // per-row partial sums
__device__ float  g_inv[(size_t)MROWS];           // 1/rowsum
__device__ __half g_o [(size_t)MROWS * HID_];
__device__ float  g_p [(size_t)MROWS * DIM_];
__device__ __half g_wt[4 * 512 * 400];            // WqT | WkT | WvT | WpT
__device__ __half g_rgbh [(size_t)MROWS * DIM_];
__device__ __half g_poseh[(size_t)MROWS * DIM_];

__device__ __forceinline__ uint32_t smem_u32(const void* p) {
    uint32_t a;
    asm("{ .reg .u64 t; cvta.to.shared.u64 t, %1; cvt.u32.u64 %0, t; }" : "=r"(a) : "l"(p));
    return a;
}
__device__ __forceinline__ void cp16(uint32_t dst, const void* src, int bytes) {
    asm volatile("cp.async.cg.shared.global [%0], [%1], 16, %2;"
                 :: "r"(dst), "l"(src), "r"(bytes));
}
#define LDSM_X4(r0, r1, r2, r3, addr)                                         \
    asm volatile("ldmatrix.sync.aligned.m8n8.x4.shared.b16 {%0,%1,%2,%3}, [%4];" \
                 : "=r"(r0), "=r"(r1), "=r"(r2), "=r"(r3) : "r"(addr))

#define MMA_F16(c, a0, a1, a2, a3, b0, b1)                                    \
    asm volatile("mma.sync.aligned.m16n8k16.row.col.f32.f16.f16.f32 "         \
                 "{%0,%1,%2,%3}, {%4,%5,%6,%7}, {%8,%9}, {%0,%1,%2,%3};"      \
                 : "+f"((c)[0]), "+f"((c)[1]), "+f"((c)[2]), "+f"((c)[3])     \
                 : "r"(a0), "r"(a1), "r"(a2), "r"(a3), "r"(b0), "r"(b1))

// FMA-pipe exp2(t), t <= ~0: rint magic + deg-5 poly for 2^frac.
__device__ __forceinline__ float fexp2(float y) {
    y = fmaxf(y, -80.0f);
    float km = y + 12582912.0f;
    int   n  = __float_as_int(km) - 0x4B400000;
    float f  = y - (km - 12582912.0f);
    float p = 1.3333558e-3f;
    p = fmaf(p, f, 9.6181291e-3f);
    p = fmaf(p, f, 5.5504109e-2f);
    p = fmaf(p, f, 2.4022651e-1f);
    p = fmaf(p, f, 6.9314718e-1f);
    p = fmaf(p, f, 1.0f);
    return __int_as_float(__float_as_int(p) + (n << 23));
}

// ---------------------------------------------------------------------------
// fp16 GEMM: C = alpha*A@B^T (+bias), f32 acc. CTA tile 128x128, 8 warps
// (warp tile 64x32), BK=64 halves, 3-stage cp.async.
// All epilogues stage the output tile in (idle) pipeline smem, then emit
// coalesced uint4 row stores.
// MODE 0: fp32 out (+bias), N-guarded (o-proj).
// MODE 3: scores — exp2(acc*c1 + c0) half + per-row partial sums -> C3.
// MODE 4: attn-v — rows scaled by bias2[global row], half out.
// MODE 5: merged q|k|v — bx<4: q (A2,Bm2,bias3 -> C3); bx 4..7: k (bias->Cv);
//         bx 8..11: vT transposed store (bias2 -> C2).
// ---------------------------------------------------------------------------
template <int MODE>
__global__ __launch_bounds__(256, 2)
void h16_mma_gemm(const __half* __restrict__ A, const __half* __restrict__ Bm,
                  const float* __restrict__ bias, const float* __restrict__ bias2,
                  void* __restrict__ Cv, __half* __restrict__ C2,
                  int N, int K,
                  long long sA, long long sB, long long sC, float alpha,
                  const __half* __restrict__ A2, const __half* __restrict__ Bm2,
                  const float* __restrict__ bias3, void* __restrict__ C3)
{
    extern __shared__ char smem[];
    const uint32_t sb = smem_u32(smem);
    const int tid = threadIdx.x;
    const int wid = tid >> 5, lane = tid & 31;
    const int warp_m = wid & 1;
    const int warp_n = wid >> 1;
    const int bx = blockIdx.x;

    const __half* Ap = A;
    const __half* Bp = Bm;
    int n0;
    if (MODE == 5) {
        if (bx < 4) { Ap = A2; Bp = Bm2; n0 = bx * 128; }
        else        { n0 = (bx - 4) * 128; }
    } else {
        n0 = bx * 128;
    }
    Ap += (long long)blockIdx.z * sA;
    Bp += (long long)blockIdx.z * sB;
    const int m0 = blockIdx.y * 128;
    const int KT = (K + 63) >> 6;

    auto load_stage = [&](int kt, int s) {
        const int k0 = kt << 6;
        const uint32_t base = sb + (uint32_t)s * 32768u;
#pragma unroll
        for (int i = 0; i < 4; i++) {
            int e = tid + (i << 8);
            int row = e >> 3, c = e & 7;
            int kk = k0 + (c << 3);
            uint32_t off = (uint32_t)(row * 128) + (uint32_t)((c ^ (row & 7)) << 4);
            const bool kin = kk < K;
            const __half* ga = Ap + (long long)(m0 + row) * K + kk;
            cp16(base + off, ga, kin ? 16 : 0);
            const bool bin = kin && (n0 + row) < N;
            const __half* gb = Bp + (long long)(n0 + row) * K + kk;
            cp16(base + 16384u + off, bin ? gb : Bp, bin ? 16 : 0);
        }
        asm volatile("cp.async.commit_group;" ::: "memory");
    };

    float acc[4][4][4];
#pragma unroll
    for (int i = 0; i < 4; i++)
#pragma unroll
        for (int j = 0; j < 4; j++)
#pragma unroll
            for (int k = 0; k < 4; k++) acc[i][j][k] = 0.f;

    const int t = lane >> 3, r = lane & 7;
    const uint32_t a_row = (uint32_t)(warp_m * 64 + (t & 1) * 8 + r);
    const uint32_t b_row = (uint32_t)(warp_n * 32 + (t & 1) * 8 + r);
    const uint32_t chb   = (uint32_t)(t >> 1);

    load_stage(0, 0);
    if (KT > 1) load_stage(1, 1);

    for (int kt = 0; kt < KT; kt++) {
        if (kt + 1 < KT) asm volatile("cp.async.wait_group 1;" ::: "memory");
        else             asm volatile("cp.async.wait_group 0;" ::: "memory");
        __syncthreads();
        if (kt + 2 < KT) load_stage(kt + 2, (kt + 2) % 3);

        const uint32_t baseA = sb + (uint32_t)(kt % 3) * 32768u;
        const uint32_t baseB = baseA + 16384u;

#pragma unroll
        for (int ks = 0; ks < 4; ks++) {
            uint32_t a[4][4], b[2][4];
#pragma unroll
            for (int mi = 0; mi < 4; mi++) {
                uint32_t addr = baseA + (a_row + mi * 16) * 128u
                              + ((((ks * 2) + chb) ^ (uint32_t)r) << 4);
                LDSM_X4(a[mi][0], a[mi][1], a[mi][2], a[mi][3], addr);
            }
#pragma unroll
            for (int j = 0; j < 2; j++) {
                uint32_t addr = baseB + (b_row + j * 16) * 128u
                              + ((((ks * 2) + chb) ^ (uint32_t)r) << 4);
                LDSM_X4(b[j][0], b[j][1], b[j][2], b[j][3], addr);
            }
#pragma unroll
            for (int mi = 0; mi < 4; mi++)
#pragma unroll
                for (int ni = 0; ni < 4; ni++)
                    MMA_F16(acc[mi][ni], a[mi][0], a[mi][1], a[mi][2], a[mi][3],
                            b[ni >> 1][ni & 1], b[ni >> 1][(ni & 1) + 2]);
        }
    }

    const int m_base_l = warp_m * 64;
    const int n_base_l = warp_n * 32;
    const int row_in = lane >> 2;
    const int col_in = (lane & 3) * 2;

    __syncthreads();                     // smem pipeline -> staging reuse

    if (MODE == 0) {
        // fp32 staging [128][PADF], bias added; N-guarded coalesced store
        float* sm = reinterpret_cast<float*>(smem);
        const int PADF = 132;
#pragma unroll
        for (int mi = 0; mi < 4; mi++) {
            const int ml = m_base_l + mi * 16 + row_in;
#pragma unroll
            for (int ni = 0; ni < 4; ni++) {
                const int nl = n_base_l + ni * 8 + col_in;
                const int gn = n0 + nl;
                float b0 = (bias && gn < N)     ? __ldg(&bias[gn])     : 0.f;
                float b1 = (bias && gn + 1 < N) ? __ldg(&bias[gn + 1]) : 0.f;
                *reinterpret_cast<float2*>(&sm[nl + ml * PADF]) =
                    make_float2(acc[mi][ni][0] * alpha + b0, acc[mi][ni][1] * alpha + b1);
                *reinterpret_cast<float2*>(&sm[nl + (ml + 8) * PADF]) =
                    make_float2(acc[mi][ni][2] * alpha + b0, acc[mi][ni][3] * alpha + b1);
            }
        }
        __syncthreads();
        float* C = (float*)Cv;
#pragma unroll
        for (int pass = 0; pass < 16; pass++) {
            int chunk = pass * 256 + tid;      // 128 rows x 32 uint4
            int row = chunk >> 5;
            int c4 = (chunk & 31) << 2;        // float offset in tile
            if (n0 + c4 < N) {                 // N multiple of 16 floats OK (400)
                uint4 v = *reinterpret_cast<uint4*>(&sm[row * PADF + c4]);
                *reinterpret_cast<uint4*>(&C[(long long)(m0 + row) * N + n0 + c4]) = v;
            }
        }
    } else if (MODE == 3) {
        // exp2(acc*c1 + c0), rowsums from f32, stage half, coalesced store
        __half* sm = reinterpret_cast<__half*>(smem);
        const int PAD = 136;
        float* rs = (float*)C3;
        const long long growb = (long long)blockIdx.z * SR_;
        const int cb = (n0 >> 5) + warp_n;
        const float c1 = alpha * 1.4426950408889634f;
        const float c0 = -8.f * 1.4426950408889634f;
#pragma unroll
        for (int mi = 0; mi < 4; mi++) {
            const int ml = m_base_l + mi * 16 + row_in;
            float s0 = 0.f, s1 = 0.f;
#pragma unroll
            for (int ni = 0; ni < 4; ni++) {
                const int nl = n_base_l + ni * 8 + col_in;
                float v00 = fexp2(fmaf(acc[mi][ni][0], c1, c0));
                float v01 = fexp2(fmaf(acc[mi][ni][1], c1, c0));
                float v10 = fexp2(fmaf(acc[mi][ni][2], c1, c0));
                float v11 = fexp2(fmaf(acc[mi][ni][3], c1, c0));
                s0 += v00 + v01;
                s1 += v10 + v11;
                *reinterpret_cast<__half2*>(&sm[nl + ml * PAD]) = __floats2half2_rn(v00, v01);
                *reinterpret_cast<__half2*>(&sm[nl + (ml + 8) * PAD]) = __floats2half2_rn(v10, v11);
            }
            s0 += __shfl_xor_sync(0xFFFFFFFFu, s0, 1);
            s0 += __shfl_xor_sync(0xFFFFFFFFu, s0, 2);
            s1 += __shfl_xor_sync(0xFFFFFFFFu, s1, 1);
            s1 += __shfl_xor_sync(0xFFFFFFFFu, s1, 2);
            if ((lane & 3) == 0) {
                rs[(growb + m0 + ml) * 64 + cb]     = s0;
                rs[(growb + m0 + ml + 8) * 64 + cb] = s1;
            }
        }
        __syncthreads();
        __half* C = (__half*)Cv + (long long)blockIdx.z * sC;
#pragma unroll
        for (int pass = 0; pass < 8; pass++) {
            int chunk = pass * 256 + tid;      // 128 rows x 16 uint4
            int row = chunk >> 4;
            int hc = (chunk & 15) << 3;        // half offset
            uint4 v = *reinterpret_cast<uint4*>(&sm[row * PAD + hc]);
            *reinterpret_cast<uint4*>(&C[(long long)(m0 + row) * N + n0 + hc]) = v;
        }
    } else if (MODE == 4) {
        // scale rows by 1/rowsum, stage half, coalesced store
        __half* sm = reinterpret_cast<__half*>(smem);
        const int PAD = 136;
        const float* rsc = bias2 + (long long)blockIdx.z * SR_;
#pragma unroll
        for (int mi = 0; mi < 4; mi++) {
            const int ml = m_base_l + mi * 16 + row_in;
            const float s0 = __ldg(&rsc[m0 + ml]);
            const float s1 = __ldg(&rsc[m0 + ml + 8]);
#pragma unroll
            for (int ni = 0; ni < 4; ni++) {
                const int nl = n_base_l + ni * 8 + col_in;
                *reinterpret_cast<__half2*>(&sm[nl + ml * PAD]) =
                    __floats2half2_rn(acc[mi][ni][0] * s0, acc[mi][ni][1] * s0);
                *reinterpret_cast<__half2*>(&sm[nl + (ml + 8) * PAD]) =
                    __floats2half2_rn(acc[mi][ni][2] * s1, acc[mi][ni][3] * s1);
            }
        }
        __syncthreads();
        __half* C = (__half*)Cv + (long long)blockIdx.z * sC;
#pragma unroll
        for (int pass = 0; pass < 8; pass++) {
            int chunk = pass * 256 + tid;
            int row = chunk >> 4;
            int hc = (chunk & 15) << 3;
            uint4 v = *reinterpret_cast<uint4*>(&sm[row * PAD + hc]);
            *reinterpret_cast<uint4*>(&C[(long long)(m0 + row) * N + n0 + hc]) = v;
        }
    } else if (MODE == 5 && bx < 8) {
        // q (bx<4 -> C3, bias3) / k (bx 4..7 -> Cv, bias); ld 512, half
        const bool qs = bx < 4;
        const float* bb = qs ? bias3 : bias;
        __half* sm = reinterpret_cast<__half*>(smem);
        const int PAD = 136;
#pragma unroll
        for (int mi = 0; mi < 4; mi++) {
            const int ml = m_base_l + mi * 16 + row_in;
#pragma unroll
            for (int ni = 0; ni < 4; ni++) {
                const int nl = n_base_l + ni * 8 + col_in;
                float b0 = bb ? __ldg(&bb[n0 + nl]) : 0.f;
                float b1 = bb ? __ldg(&bb[n0 + nl + 1]) : 0.f;
                *reinterpret_cast<__half2*>(&sm[nl + ml * PAD]) =
                    __floats2half2_rn(acc[mi][ni][0] + b0, acc[mi][ni][1] + b1);
                *reinterpret_cast<__half2*>(&sm[nl + (ml + 8) * PAD]) =
                    __floats2half2_rn(acc[mi][ni][2] + b0, acc[mi][ni][3] + b1);
            }
        }
        __syncthreads();
        __half* C = qs ? (__half*)C3 : (__half*)Cv;
#pragma unroll
        for (int pass = 0; pass < 8; pass++) {
            int chunk = pass * 256 + tid;
            int row = chunk >> 4;
            int hc = (chunk & 15) << 3;
            uint4 v = *reinterpret_cast<uint4*>(&sm[row * PAD + hc]);
            *reinterpret_cast<uint4*>(&C[(long long)(m0 + row) * 512 + n0 + hc]) = v;
        }
    } else {
        // MODE5 v side: vT[b][h][p], h = gn - 512. Stage [n][m] in smem.
        __half* sm = reinterpret_cast<__half*>(smem);
        const int PAD = 136;
        const int h0 = n0 - 512;
#pragma unroll
        for (int mi = 0; mi < 4; mi++) {
            const int ml = m_base_l + mi * 16 + row_in;
#pragma unroll
            for (int ni = 0; ni < 4; ni++) {
                const int nl = n_base_l + ni * 8 + col_in;
                float b0 = bias2 ? __ldg(&bias2[h0 + nl]) : 0.f;
                float b1 = bias2 ? __ldg(&bias2[h0 + nl + 1]) : 0.f;
                sm[nl * PAD + ml]           = __float2half_rn(acc[mi][ni][0] + b0);
                sm[(nl + 1) * PAD + ml]     = __float2half_rn(acc[mi][ni][1] + b1);
                sm[nl * PAD + ml + 8]       = __float2half_rn(acc[mi][ni][2] + b0);
                sm[(nl + 1) * PAD + ml + 8] = __float2half_rn(acc[mi][ni][3] + b1);
            }
        }
        __syncthreads();
        const long long obase = ((long long)(m0 >> 11) << 20) + (m0 & 2047);
#pragma unroll
        for (int pass = 0; pass < 8; pass++) {
            int chunk = pass * 256 + tid;
            int n = chunk >> 4;
            int mc = (chunk & 15) << 3;
            uint4 v = *reinterpret_cast<uint4*>(&sm[n * PAD + mc]);
            *reinterpret_cast<uint4*>(&C2[obase + ((long long)(h0 + n) << 11) + mc]) = v;
        }
    }
}

// ---------------------------------------------------------------------------
// prep (merged): rgb/pose -> half copies; weight transpose -> half.
// ---------------------------------------------------------------------------
__global__ __launch_bounds__(256)
void prep_kernel(const float* __restrict__ rgb, const float* __restrict__ pose,
                 __half* __restrict__ rgbh, __half* __restrict__ poseh,
                 const float* __restrict__ Wq, const float* __restrict__ Wk,
                 const float* __restrict__ Wv, const float* __restrict__ Wp,
                 __half* __restrict__ wt)
{
    const long long NEL4 = (long long)MROWS * DIM_ / 4;
    const int SZ = 512 * 400;
    long long idx = (long long)blockIdx.x * 256 + threadIdx.x;
    if (idx < 2 * NEL4) {
        const float* src = (idx < NEL4) ? rgb : pose;
        __half* dst = (idx < NEL4) ? rgbh : poseh;
        long long j = (idx < NEL4) ? idx : idx - NEL4;
        float4 v = reinterpret_cast<const float4*>(src)[j];
        __half2 h0 = __floats2half2_rn(v.x, v.y);
        __half2 h1 = __floats2half2_rn(v.z, v.w);
        reinterpret_cast<uint2*>(dst)[j] = make_uint2(
            *reinterpret_cast<uint32_t*>(&h0), *reinterpret_cast<uint32_t*>(&h1));
        return;
    }
    long long wi = idx - 2 * NEL4;
    if (wi < 3 * SZ) {
        int w = (int)(wi / SZ), rr = (int)(wi % SZ);
        int h = rr / 400, dd = rr % 400;
        const float* W = (w == 0) ? Wq : (w == 1) ? Wk : Wv;
        wt[wi] = __float2half_rn(W[dd * 512 + h]);
    } else if (wi < 4 * SZ) {
        int rr = (int)(wi - 3 * SZ);
        int n = rr / 512, kk = rr % 512;
        wt[wi] = __float2half_rn(Wp[kk * 400 + n]);
    }
}

// ---------------------------------------------------------------------------
// inv[row] = 1 / sum(partials[row][0..63]). One warp per row.
// ---------------------------------------------------------------------------
__global__ __launch_bounds__(256)
void inv_kernel(const float* __restrict__ rs, float* __restrict__ inv)
{
    const int row = blockIdx.x * 8 + (threadIdx.x >> 5);
    const int lane = threadIdx.x & 31;
    const float* r = rs + (long long)row * 64;
    float s = r[lane] + r[lane + 32];
#pragma unroll
    for (int d = 16; d > 0; d >>= 1)
        s += __shfl_xor_sync(0xFFFFFFFFu, s, d);
    if (lane == 0) inv[row] = 1.f / s;
}

// ---------------------------------------------------------------------------
// x = rgb + gate*proj ; out = LN(x)*gamma + beta
// ---------------------------------------------------------------------------
__global__ __launch_bounds__(256)
void residual_ln_kernel(const float* __restrict__ proj, const float* __restrict__ rgb,
                        const float* __restrict__ gamma, const float* __restrict__ beta,
                        const float* __restrict__ gate, float* __restrict__ out)
{
    const long long row = blockIdx.x;
    const float g = gate[0];
    const float* pr = proj + row * DIM_;
    const float* rr = rgb + row * DIM_;
    float* orow = out + row * DIM_;
    const int tid = threadIdx.x;
    const int i1 = tid + 256;
    const bool has1 = (i1 < DIM_);

    float x0 = rr[tid] + g * pr[tid];
    float x1 = has1 ? (rr[i1] + g * pr[i1]) : 0.f;

    __shared__ float rs[256], rs2[256];
    rs[tid] = x0 + x1;
    rs2[tid] = x0 * x0 + x1 * x1;
    __syncthreads();
#pragma unroll
    for (int s = 128; s > 0; s >>= 1) {
        if (tid < s) { rs[tid] += rs[tid + s]; rs2[tid] += rs2[tid + s]; }
        __syncthreads();
    }
    const float mean = rs[0] * (1.f / DIM_);
    const float var  = rs2[0] * (1.f / DIM_) - mean * mean;
    const float inv  = rsqrtf(var + 1e-5f);

    orow[tid] = (x0 - mean) * inv * gamma[tid] + beta[tid];
    if (has1) orow[i1] = (x1 - mean) * inv * gamma[i1] + beta[i1];
}

// ---------------------------------------------------------------------------
// Launch
// ---------------------------------------------------------------------------
extern "C" void kernel_launch(void* const* d_in, const int* in_sizes, int n_in,
                              void* d_out, int out_size)
{
    const float* rgb  = (const float*)d_in[0];
    const float* pose = (const float*)d_in[1];
    const float* Wq   = (const float*)d_in[2];
    const float* bq   = (const float*)d_in[3];
    const float* Wk   = (const float*)d_in[4];
    const float* bk   = (const float*)d_in[5];
    const float* Wv   = (const float*)d_in[6];
    const float* bv   = (const float*)d_in[7];
    const float* Wp   = (const float*)d_in[8];
    const float* bp   = (const float*)d_in[9];
    const float* lng  = (const float*)d_in[10];
    const float* lnb  = (const float*)d_in[11];
    const float* gate = (const float*)d_in[12];
    float* out = (float*)d_out;

    __half *q, *k, *vt, *pu, *o, *wt, *rgbh, *poseh;
    float *p, *inv, *rs;
    cudaGetSymbolAddress((void**)&q,  g_q);
    cudaGetSymbolAddress((void**)&k,  g_k);
    cudaGetSymbolAddress((void**)&vt, g_vt);
    cudaGetSymbolAddress((void**)&pu, g_pu);
    cudaGetSymbolAddress((void**)&rs, g_rs);
    cudaGetSymbolAddress((void**)&inv, g_inv);
    cudaGetSymbolAddress((void**)&o,  g_o);
    cudaGetSymbolAddress((void**)&p,  g_p);
    cudaGetSymbolAddress((void**)&wt, g_wt);
    cudaGetSymbolAddress((void**)&rgbh,  g_rgbh);
    cudaGetSymbolAddress((void**)&poseh, g_poseh);

    const int SMEM = 3 * 32768;        // 96 KB
    cudaFuncSetAttribute(h16_mma_gemm<0>, cudaFuncAttributeMaxDynamicSharedMemorySize, SMEM);
    cudaFuncSetAttribute(h16_mma_gemm<3>, cudaFuncAttributeMaxDynamicSharedMemorySize, SMEM);
    cudaFuncSetAttribute(h16_mma_gemm<4>, cudaFuncAttributeMaxDynamicSharedMemorySize, SMEM);
    cudaFuncSetAttribute(h16_mma_gemm<5>, cudaFuncAttributeMaxDynamicSharedMemorySize, SMEM);

    const int WSZ = 512 * 400;

    // 0. prep (input halving + weight transpose, one launch)
    {
        long long total = 2LL * MROWS * DIM_ / 4 + 4LL * WSZ;
        prep_kernel<<<(unsigned)((total + 255) / 256), 256>>>(
            rgb, pose, rgbh, poseh, Wq, Wk, Wv, Wp, wt);
    }

    // 1. merged q|k|v projection
    {
        dim3 grid(12, MROWS / 128, 1);
        h16_mma_gemm<5><<<grid, 256, SMEM>>>(
            poseh, wt + WSZ, bk, bv, k, vt, 1024, DIM_, 0, 0, 0, 1.f,
            rgbh, wt, bq, q);
    }
    // 2. probs_unnorm = exp(q@k^T/sqrt(512) - 8) + partial row sums
    {
        dim3 grid(SP_ / 128, SR_ / 128, B_);
        h16_mma_gemm<3><<<grid, 256, SMEM>>>(
            q, k, nullptr, nullptr, pu, nullptr, SP_, HID_,
            (long long)SR_ * HID_, (long long)SP_ * HID_,
            (long long)SR_ * SP_, 0.044194173824159216f,
            nullptr, nullptr, nullptr, rs);
    }
    // 3. inv = 1/rowsum
    inv_kernel<<<MROWS / 8, 256>>>(rs, inv);

    // 4. O = (probs_unnorm @ v) * inv[row]
    {
        dim3 grid(HID_ / 128, SR_ / 128, B_);
        h16_mma_gemm<4><<<grid, 256, SMEM>>>(
            pu, vt, nullptr, inv, o, nullptr, HID_, SP_,
            (long long)SR_ * SP_, (long long)HID_ * SP_,
            (long long)SR_ * HID_, 1.f,
            nullptr, nullptr, nullptr, nullptr);
    }
    // 5. proj = O @ Wp + bp -> fp32
    {
        dim3 grid((DIM_ + 127) / 128, MROWS / 128, 1);
        h16_mma_gemm<0><<<grid, 256, SMEM>>>(
            o, wt + 3 * WSZ, bp, nullptr, p, nullptr, DIM_, HID_, 0, 0, 0, 1.f,
            nullptr, nullptr, nullptr, nullptr);
    }
    // 6. residual + LayerNorm
    residual_ln_kernel<<<MROWS, 256>>>(p, rgb, lng, lnb, gate, out);
}

// round 15
// speedup vs baseline: 1.0654x; 1.0059x over previous
#include <cuda_runtime.h>
#include <cuda_fp16.h>
#include <cstdint>
#include <math.h>

// ---------------------------------------------------------------------------
// CrossModalFusion, fp16 mma.sync (m16n8k16, f32 acc).
// R15: K templated (KTOT) — partial last K-iteration executes only the
// k16-steps covering real data (kills the 448-vs-400 padding waste).
// B=32, Sr=Sp=2048, D=400, H=512
// ---------------------------------------------------------------------------
#define B_   32
#define SR_  2048
#define SP_  2048
#define DIM_ 400
#define HID_ 512
#define MROWS (B_ * SR_)          // 65536

__device__ __half g_q [(size_t)MROWS * HID_];
__device__ __half g_k [(size_t)MROWS * HID_];
__device__ __half g_vt[(size_t)MROWS * HID_];     // [B][H][Sp]
__device__ __half g_pu[(size_t)B_ * SR_ * SP_];   // unnormalized probs (half)
__device__ float  g_rs[(size_t)MROWS * 64];       // per-row partial sums
__device__ float  g_inv[(size_t)MROWS];           // 1/rowsum
__device__ __half g_o [(size_t)MROWS * HID_];
__device__ float  g_p [(size_t)MROWS * DIM_];
__device__ __half g_wt[4 * 512 * 400];            // WqT | WkT | WvT | WpT
__device__ __half g_rgbh [(size_t)MROWS * DIM_];
__device__ __half g_poseh[(size_t)MROWS * DIM_];

__device__ __forceinline__ uint32_t smem_u32(const void* p) {
    uint32_t a;
    asm("{ .reg .u64 t; cvta.to.shared.u64 t, %1; cvt.u32.u64 %0, t; }" : "=r"(a) : "l"(p));
    return a;
}
__device__ __forceinline__ void cp16(uint32_t dst, const void* src, int bytes) {
    asm volatile("cp.async.cg.shared.global [%0], [%1], 16, %2;"
                 :: "r"(dst), "l"(src), "r"(bytes));
}
#define LDSM_X4(r0, r1, r2, r3, addr)                                         \
    asm volatile("ldmatrix.sync.aligned.m8n8.x4.shared.b16 {%0,%1,%2,%3}, [%4];" \
                 : "=r"(r0), "=r"(r1), "=r"(r2), "=r"(r3) : "r"(addr))

#define MMA_F16(c, a0, a1, a2, a3, b0, b1)                                    \
    asm volatile("mma.sync.aligned.m16n8k16.row.col.f32.f16.f16.f32 "         \
                 "{%0,%1,%2,%3}, {%4,%5,%6,%7}, {%8,%9}, {%0,%1,%2,%3};"      \
                 : "+f"((c)[0]), "+f"((c)[1]), "+f"((c)[2]), "+f"((c)[3])     \
                 : "r"(a0), "r"(a1), "r"(a2), "r"(a3), "r"(b0), "r"(b1))

// FMA-pipe exp2(t): rint magic + deg-5 poly for 2^frac (abs err ~2.4e-6).
__device__ __forceinline__ float fexp2(float y) {
    y = fmaxf(y, -80.0f);
    float km = y + 12582912.0f;
    int   n  = __float_as_int(km) - 0x4B400000;
    float f  = y - (km - 12582912.0f);
    float p = 1.3333558e-3f;
    p = fmaf(p, f, 9.6181291e-3f);
    p = fmaf(p, f, 5.5504109e-2f);
    p = fmaf(p, f, 2.4022651e-1f);
    p = fmaf(p, f, 6.9314718e-1f);
    p = fmaf(p, f, 1.0f);
    return __int_as_float(__float_as_int(p) + (n << 23));
}

// ---------------------------------------------------------------------------
// fp16 GEMM: C = alpha*A@B^T (+bias), f32 acc. CTA tile 128x128, 8 warps
// (warp tile 64x32), BK=64 halves, 3-stage cp.async. K = KTOT (compile-time);
// last iteration runs only ceil((KTOT mod 64)/16) k16-steps.
// Epilogues stage in idle pipeline smem -> coalesced uint4 stores.
// MODE 0: fp32 out (+bias), N-guarded (o-proj).
// MODE 3: scores — exp2(acc*c1 + c0) half + per-row partial sums -> C3.
// MODE 4: attn-v — rows scaled by bias2[global row], half out.
// MODE 5: merged q|k|v — bx<4: q (A2,Bm2,bias3 -> C3); bx 4..7: k (bias->Cv);
//         bx 8..11: vT transposed store (bias2 -> C2).
// ---------------------------------------------------------------------------
template <int MODE, int KTOT>
__global__ __launch_bounds__(256, 2)
void h16_mma_gemm(const __half* __restrict__ A, const __half* __restrict__ Bm,
                  const float* __restrict__ bias, const float* __restrict__ bias2,
                  void* __restrict__ Cv, __half* __restrict__ C2,
                  int N,
                  long long sA, long long sB, long long sC, float alpha,
                  const __half* __restrict__ A2, const __half* __restrict__ Bm2,
                  const float* __restrict__ bias3, void* __restrict__ C3)
{
    constexpr int KT = (KTOT + 63) >> 6;
    constexpr int KS_TAIL = ((KTOT - ((KT - 1) << 6)) + 15) >> 4;   // 1..4

    extern __shared__ char smem[];
    const uint32_t sb = smem_u32(smem);
    const int tid = threadIdx.x;
    const int wid = tid >> 5, lane = tid & 31;
    const int warp_m = wid & 1;
    const int warp_n = wid >> 1;
    const int bx = blockIdx.x;

    const __half* Ap = A;
    const __half* Bp = Bm;
    int n0;
    if (MODE == 5) {
        if (bx < 4) { Ap = A2; Bp = Bm2; n0 = bx * 128; }
        else        { n0 = (bx - 4) * 128; }
    } else {
        n0 = bx * 128;
    }
    Ap += (long long)blockIdx.z * sA;
    Bp += (long long)blockIdx.z * sB;
    const int m0 = blockIdx.y * 128;

    auto load_stage = [&](int kt, int s) {
        const int k0 = kt << 6;
        const uint32_t base = sb + (uint32_t)s * 32768u;
#pragma unroll
        for (int i = 0; i < 4; i++) {
            int e = tid + (i << 8);
            int row = e >> 3, c = e & 7;
            int kk = k0 + (c << 3);
            uint32_t off = (uint32_t)(row * 128) + (uint32_t)((c ^ (row & 7)) << 4);
            const bool kin = kk < KTOT;
            const __half* ga = Ap + (long long)(m0 + row) * KTOT + kk;
            cp16(base + off, ga, kin ? 16 : 0);
            const bool bin = kin && (n0 + row) < N;
            const __half* gb = Bp + (long long)(n0 + row) * KTOT + kk;
            cp16(base + 16384u + off, bin ? gb : Bp, bin ? 16 : 0);
        }
        asm volatile("cp.async.commit_group;" ::: "memory");
    };

    float acc[4][4][4];
#pragma unroll
    for (int i = 0; i < 4; i++)
#pragma unroll
        for (int j = 0; j < 4; j++)
#pragma unroll
            for (int k = 0; k < 4; k++) acc[i][j][k] = 0.f;

    const int t = lane >> 3, r = lane & 7;
    const uint32_t a_row = (uint32_t)(warp_m * 64 + (t & 1) * 8 + r);
    const uint32_t b_row = (uint32_t)(warp_n * 32 + (t & 1) * 8 + r);
    const uint32_t chb   = (uint32_t)(t >> 1);

    load_stage(0, 0);
    if (KT > 1) load_stage(1, 1);

    for (int kt = 0; kt < KT; kt++) {
        if (kt + 1 < KT) asm volatile("cp.async.wait_group 1;" ::: "memory");
        else             asm volatile("cp.async.wait_group 0;" ::: "memory");
        __syncthreads();
        if (kt + 2 < KT) load_stage(kt + 2, (kt + 2) % 3);

        const uint32_t baseA = sb + (uint32_t)(kt % 3) * 32768u;
        const uint32_t baseB = baseA + 16384u;
        const int nks = (kt == KT - 1) ? KS_TAIL : 4;

#pragma unroll
        for (int ks = 0; ks < 4; ks++) {
            if (ks >= nks) break;
            uint32_t a[4][4], b[2][4];
#pragma unroll
            for (int mi = 0; mi < 4; mi++) {
                uint32_t addr = baseA + (a_row + mi * 16) * 128u
                              + ((((ks * 2) + chb) ^ (uint32_t)r) << 4);
                LDSM_X4(a[mi][0], a[mi][1], a[mi][2], a[mi][3], addr);
            }
#pragma unroll
            for (int j = 0; j < 2; j++) {
                uint32_t addr = baseB + (b_row + j * 16) * 128u
                              + ((((ks * 2) + chb) ^ (uint32_t)r) << 4);
                LDSM_X4(b[j][0], b[j][1], b[j][2], b[j][3], addr);
            }
#pragma unroll
            for (int mi = 0; mi < 4; mi++)
#pragma unroll
                for (int ni = 0; ni < 4; ni++)
                    MMA_F16(acc[mi][ni], a[mi][0], a[mi][1], a[mi][2], a[mi][3],
                            b[ni >> 1][ni & 1], b[ni >> 1][(ni & 1) + 2]);
        }
    }

    const int m_base_l = warp_m * 64;
    const int n_base_l = warp_n * 32;
    const int row_in = lane >> 2;
    const int col_in = (lane & 3) * 2;

    __syncthreads();                     // smem pipeline -> staging reuse

    if (MODE == 0) {
        float* sm = reinterpret_cast<float*>(smem);
        const int PADF = 132;
#pragma unroll
        for (int mi = 0; mi < 4; mi++) {
            const int ml = m_base_l + mi * 16 + row_in;
#pragma unroll
            for (int ni = 0; ni < 4; ni++) {
                const int nl = n_base_l + ni * 8 + col_in;
                const int gn = n0 + nl;
                float b0 = (bias && gn < N)     ? __ldg(&bias[gn])     : 0.f;
                float b1 = (bias && gn + 1 < N) ? __ldg(&bias[gn + 1]) : 0.f;
                *reinterpret_cast<float2*>(&sm[nl + ml * PADF]) =
                    make_float2(acc[mi][ni][0] * alpha + b0, acc[mi][ni][1] * alpha + b1);
                *reinterpret_cast<float2*>(&sm[nl + (ml + 8) * PADF]) =
                    make_float2(acc[mi][ni][2] * alpha + b0, acc[mi][ni][3] * alpha + b1);
            }
        }
        __syncthreads();
        float* C = (float*)Cv;
#pragma unroll
        for (int pass = 0; pass < 16; pass++) {
            int chunk = pass * 256 + tid;
            int row = chunk >> 5;
            int c4 = (chunk & 31) << 2;
            if (n0 + c4 < N) {
                uint4 v = *reinterpret_cast<uint4*>(&sm[row * PADF + c4]);
                *reinterpret_cast<uint4*>(&C[(long long)(m0 + row) * N + n0 + c4]) = v;
            }
        }
    } else if (MODE == 3) {
        __half* sm = reinterpret_cast<__half*>(smem);
        const int PAD = 136;
        float* rs = (float*)C3;
        const long long growb = (long long)blockIdx.z * SR_;
        const int cb = (n0 >> 5) + warp_n;
        const float c1 = alpha * 1.4426950408889634f;
        const float c0 = -8.f * 1.4426950408889634f;
#pragma unroll
        for (int mi = 0; mi < 4; mi++) {
            const int ml = m_base_l + mi * 16 + row_in;
            float s0 = 0.f, s1 = 0.f;
#pragma unroll
            for (int ni = 0; ni < 4; ni++) {
                const int nl = n_base_l + ni * 8 + col_in;
                float v00 = fexp2(fmaf(acc[mi][ni][0], c1, c0));
                float v01 = fexp2(fmaf(acc[mi][ni][1], c1, c0));
                float v10 = fexp2(fmaf(acc[mi][ni][2], c1, c0));
                float v11 = fexp2(fmaf(acc[mi][ni][3], c1, c0));
                s0 += v00 + v01;
                s1 += v10 + v11;
                *reinterpret_cast<__half2*>(&sm[nl + ml * PAD]) = __floats2half2_rn(v00, v01);
                *reinterpret_cast<__half2*>(&sm[nl + (ml + 8) * PAD]) = __floats2half2_rn(v10, v11);
            }
            s0 += __shfl_xor_sync(0xFFFFFFFFu, s0, 1);
            s0 += __shfl_xor_sync(0xFFFFFFFFu, s0, 2);
            s1 += __shfl_xor_sync(0xFFFFFFFFu, s1, 1);
            s1 += __shfl_xor_sync(0xFFFFFFFFu, s1, 2);
            if ((lane & 3) == 0) {
                rs[(growb + m0 + ml) * 64 + cb]     = s0;
                rs[(growb + m0 + ml + 8) * 64 + cb] = s1;
            }
        }
        __syncthreads();
        __half* C = (__half*)Cv + (long long)blockIdx.z * sC;
#pragma unroll
        for (int pass = 0; pass < 8; pass++) {
            int chunk = pass * 256 + tid;
            int row = chunk >> 4;
            int hc = (chunk & 15) << 3;
            uint4 v = *reinterpret_cast<uint4*>(&sm[row * PAD + hc]);
            *reinterpret_cast<uint4*>(&C[(long long)(m0 + row) * N + n0 + hc]) = v;
        }
    } else if (MODE == 4) {
        __half* sm = reinterpret_cast<__half*>(smem);
        const int PAD = 136;
        const float* rsc = bias2 + (long long)blockIdx.z * SR_;
#pragma unroll
        for (int mi = 0; mi < 4; mi++) {
            const int ml = m_base_l + mi * 16 + row_in;
            const float s0 = __ldg(&rsc[m0 + ml]);
            const float s1 = __ldg(&rsc[m0 + ml + 8]);
#pragma unroll
            for (int ni = 0; ni < 4; ni++) {
                const int nl = n_base_l + ni * 8 + col_in;
                *reinterpret_cast<__half2*>(&sm[nl + ml * PAD]) =
                    __floats2half2_rn(acc[mi][ni][0] * s0, acc[mi][ni][1] * s0);
                *reinterpret_cast<__half2*>(&sm[nl + (ml + 8) * PAD]) =
                    __floats2half2_rn(acc[mi][ni][2] * s1, acc[mi][ni][3] * s1);
            }
        }
        __syncthreads();
        __half* C = (__half*)Cv + (long long)blockIdx.z * sC;
#pragma unroll
        for (int pass = 0; pass < 8; pass++) {
            int chunk = pass * 256 + tid;
            int row = chunk >> 4;
            int hc = (chunk & 15) << 3;
            uint4 v = *reinterpret_cast<uint4*>(&sm[row * PAD + hc]);
            *reinterpret_cast<uint4*>(&C[(long long)(m0 + row) * N + n0 + hc]) = v;
        }
    } else if (MODE == 5 && bx < 8) {
        const bool qs = bx < 4;
        const float* bb = qs ? bias3 : bias;
        __half* sm = reinterpret_cast<__half*>(smem);
        const int PAD = 136;
#pragma unroll
        for (int mi = 0; mi < 4; mi++) {
            const int ml = m_base_l + mi * 16 + row_in;
#pragma unroll
            for (int ni = 0; ni < 4; ni++) {
                const int nl = n_base_l + ni * 8 + col_in;
                float b0 = bb ? __ldg(&bb[n0 + nl]) : 0.f;
                float b1 = bb ? __ldg(&bb[n0 + nl + 1]) : 0.f;
                *reinterpret_cast<__half2*>(&sm[nl + ml * PAD]) =
                    __floats2half2_rn(acc[mi][ni][0] + b0, acc[mi][ni][1] + b1);
                *reinterpret_cast<__half2*>(&sm[nl + (ml + 8) * PAD]) =
                    __floats2half2_rn(acc[mi][ni][2] + b0, acc[mi][ni][3] + b1);
            }
        }
        __syncthreads();
        __half* C = qs ? (__half*)C3 : (__half*)Cv;
#pragma unroll
        for (int pass = 0; pass < 8; pass++) {
            int chunk = pass * 256 + tid;
            int row = chunk >> 4;
            int hc = (chunk & 15) << 3;
            uint4 v = *reinterpret_cast<uint4*>(&sm[row * PAD + hc]);
            *reinterpret_cast<uint4*>(&C[(long long)(m0 + row) * 512 + n0 + hc]) = v;
        }
    } else {
        // MODE5 v side: vT[b][h][p], h = gn - 512. Stage [n][m] in smem.
        __half* sm = reinterpret_cast<__half*>(smem);
        const int PAD = 136;
        const int h0 = n0 - 512;
#pragma unroll
        for (int mi = 0; mi < 4; mi++) {
            const int ml = m_base_l + mi * 16 + row_in;
#pragma unroll
            for (int ni = 0; ni < 4; ni++) {
                const int nl = n_base_l + ni * 8 + col_in;
                float b0 = bias2 ? __ldg(&bias2[h0 + nl]) : 0.f;
                float b1 = bias2 ? __ldg(&bias2[h0 + nl + 1]) : 0.f;
                sm[nl * PAD + ml]           = __float2half_rn(acc[mi][ni][0] + b0);
                sm[(nl + 1) * PAD + ml]     = __float2half_rn(acc[mi][ni][1] + b1);
                sm[nl * PAD + ml + 8]       = __float2half_rn(acc[mi][ni][2] + b0);
                sm[(nl + 1) * PAD + ml + 8] = __float2half_rn(acc[mi][ni][3] + b1);
            }
        }
        __syncthreads();
        const long long obase = ((long long)(m0 >> 11) << 20) + (m0 & 2047);
#pragma unroll
        for (int pass = 0; pass < 8; pass++) {
            int chunk = pass * 256 + tid;
            int n = chunk >> 4;
            int mc = (chunk & 15) << 3;
            uint4 v = *reinterpret_cast<uint4*>(&sm[n * PAD + mc]);
            *reinterpret_cast<uint4*>(&C2[obase + ((long long)(h0 + n) << 11) + mc]) = v;
        }
    }
}

// ---------------------------------------------------------------------------
// prep (merged): rgb/pose -> half copies; weight transpose -> half.
// ---------------------------------------------------------------------------
__global__ __launch_bounds__(256)
void prep_kernel(const float* __restrict__ rgb, const float* __restrict__ pose,
                 __half* __restrict__ rgbh, __half* __restrict__ poseh,
                 const float* __restrict__ Wq, const float* __restrict__ Wk,
                 const float* __restrict__ Wv, const float* __restrict__ Wp,
                 __half* __restrict__ wt)
{
    const long long NEL4 = (long long)MROWS * DIM_ / 4;
    const int SZ = 512 * 400;
    long long idx = (long long)blockIdx.x * 256 + threadIdx.x;
    if (idx < 2 * NEL4) {
        const float* src = (idx < NEL4) ? rgb : pose;
        __half* dst = (idx < NEL4) ? rgbh : poseh;
        long long j = (idx < NEL4) ? idx : idx - NEL4;
        float4 v = reinterpret_cast<const float4*>(src)[j];
        __half2 h0 = __floats2half2_rn(v.x, v.y);
        __half2 h1 = __floats2half2_rn(v.z, v.w);
        reinterpret_cast<uint2*>(dst)[j] = make_uint2(
            *reinterpret_cast<uint32_t*>(&h0), *reinterpret_cast<uint32_t*>(&h1));
        return;
    }
    long long wi = idx - 2 * NEL4;
    if (wi < 3 * SZ) {
        int w = (int)(wi / SZ), rr = (int)(wi % SZ);
        int h = rr / 400, dd = rr % 400;
        const float* W = (w == 0) ? Wq : (w == 1) ? Wk : Wv;
        wt[wi] = __float2half_rn(W[dd * 512 + h]);
    } else if (wi < 4 * SZ) {
        int rr = (int)(wi - 3 * SZ);
        int n = rr / 512, kk = rr % 512;
        wt[wi] = __float2half_rn(Wp[kk * 400 + n]);
    }
}

// ---------------------------------------------------------------------------
// inv[row] = 1 / sum(partials[row][0..63]). One warp per row.
// ---------------------------------------------------------------------------
__global__ __launch_bounds__(256)
void inv_kernel(const float* __restrict__ rs, float* __restrict__ inv)
{
    const int row = blockIdx.x * 8 + (threadIdx.x >> 5);
    const int lane = threadIdx.x & 31;
    const float* r = rs + (long long)row * 64;
    float s = r[lane] + r[lane + 32];
#pragma unroll
    for (int d = 16; d > 0; d >>= 1)
        s += __shfl_xor_sync(0xFFFFFFFFu, s, d);
    if (lane == 0) inv[row] = 1.f / s;
}

// ---------------------------------------------------------------------------
// x = rgb + gate*proj ; out = LN(x)*gamma + beta
// ---------------------------------------------------------------------------
__global__ __launch_bounds__(256)
void residual_ln_kernel(const float* __restrict__ proj, const float* __restrict__ rgb,
                        const float* __restrict__ gamma, const float* __restrict__ beta,
                        const float* __restrict__ gate, float* __restrict__ out)
{
    const long long row = blockIdx.x;
    const float g = gate[0];
    const float* pr = proj + row * DIM_;
    const float* rr = rgb + row * DIM_;
    float* orow = out + row * DIM_;
    const int tid = threadIdx.x;
    const int i1 = tid + 256;
    const bool has1 = (i1 < DIM_);

    float x0 = rr[tid] + g * pr[tid];
    float x1 = has1 ? (rr[i1] + g * pr[i1]) : 0.f;

    __shared__ float rs[256], rs2[256];
    rs[tid] = x0 + x1;
    rs2[tid] = x0 * x0 + x1 * x1;
    __syncthreads();
#pragma unroll
    for (int s = 128; s > 0; s >>= 1) {
        if (tid < s) { rs[tid] += rs[tid + s]; rs2[tid] += rs2[tid + s]; }
        __syncthreads();
    }
    const float mean = rs[0] * (1.f / DIM_);
    const float var  = rs2[0] * (1.f / DIM_) - mean * mean;
    const float inv  = rsqrtf(var + 1e-5f);

    orow[tid] = (x0 - mean) * inv * gamma[tid] + beta[tid];
    if (has1) orow[i1] = (x1 - mean) * inv * gamma[i1] + beta[i1];
}

// ---------------------------------------------------------------------------
// Launch
// ---------------------------------------------------------------------------
extern "C" void kernel_launch(void* const* d_in, const int* in_sizes, int n_in,
                              void* d_out, int out_size)
{
    const float* rgb  = (const float*)d_in[0];
    const float* pose = (const float*)d_in[1];
    const float* Wq   = (const float*)d_in[2];
    const float* bq   = (const float*)d_in[3];
    const float* Wk   = (const float*)d_in[4];
    const float* bk   = (const float*)d_in[5];
    const float* Wv   = (const float*)d_in[6];
    const float* bv   = (const float*)d_in[7];
    const float* Wp   = (const float*)d_in[8];
    const float* bp   = (const float*)d_in[9];
    const float* lng  = (const float*)d_in[10];
    const float* lnb  = (const float*)d_in[11];
    const float* gate = (const float*)d_in[12];
    float* out = (float*)d_out;

    __half *q, *k, *vt, *pu, *o, *wt, *rgbh, *poseh;
    float *p, *inv, *rs;
    cudaGetSymbolAddress((void**)&q,  g_q);
    cudaGetSymbolAddress((void**)&k,  g_k);
    cudaGetSymbolAddress((void**)&vt, g_vt);
    cudaGetSymbolAddress((void**)&pu, g_pu);
    cudaGetSymbolAddress((void**)&rs, g_rs);
    cudaGetSymbolAddress((void**)&inv, g_inv);
    cudaGetSymbolAddress((void**)&o,  g_o);
    cudaGetSymbolAddress((void**)&p,  g_p);
    cudaGetSymbolAddress((void**)&wt, g_wt);
    cudaGetSymbolAddress((void**)&rgbh,  g_rgbh);
    cudaGetSymbolAddress((void**)&poseh, g_poseh);

    const int SMEM = 3 * 32768;        // 96 KB
    cudaFuncSetAttribute(h16_mma_gemm<0,512>,  cudaFuncAttributeMaxDynamicSharedMemorySize, SMEM);
    cudaFuncSetAttribute(h16_mma_gemm<3,512>,  cudaFuncAttributeMaxDynamicSharedMemorySize, SMEM);
    cudaFuncSetAttribute(h16_mma_gemm<4,2048>, cudaFuncAttributeMaxDynamicSharedMemorySize, SMEM);
    cudaFuncSetAttribute(h16_mma_gemm<5,400>,  cudaFuncAttributeMaxDynamicSharedMemorySize, SMEM);

    const int WSZ = 512 * 400;

    // 0. prep (input halving + weight transpose, one launch)
    {
        long long total = 2LL * MROWS * DIM_ / 4 + 4LL * WSZ;
        prep_kernel<<<(unsigned)((total + 255) / 256), 256>>>(
            rgb, pose, rgbh, poseh, Wq, Wk, Wv, Wp, wt);
    }

    // 1. merged q|k|v projection (K=400; tail iter runs 1 k16-step)
    {
        dim3 grid(12, MROWS / 128, 1);
        h16_mma_gemm<5,400><<<grid, 256, SMEM>>>(
            poseh, wt + WSZ, bk, bv, k, vt, 1024, 0, 0, 0, 1.f,
            rgbh, wt, bq, q);
    }
    // 2. probs_unnorm = exp(q@k^T/sqrt(512) - 8) + partial row sums
    {
        dim3 grid(SP_ / 128, SR_ / 128, B_);
        h16_mma_gemm<3,512><<<grid, 256, SMEM>>>(
            q, k, nullptr, nullptr, pu, nullptr, SP_,
            (long long)SR_ * HID_, (long long)SP_ * HID_,
            (long long)SR_ * SP_, 0.044194173824159216f,
            nullptr, nullptr, nullptr, rs);
    }
    // 3. inv = 1/rowsum
    inv_kernel<<<MROWS / 8, 256>>>(rs, inv);

    // 4. O = (probs_unnorm @ v) * inv[row]
    {
        dim3 grid(HID_ / 128, SR_ / 128, B_);
        h16_mma_gemm<4,2048><<<grid, 256, SMEM>>>(
            pu, vt, nullptr, inv, o, nullptr, HID_,
            (long long)SR_ * SP_, (long long)HID_ * SP_,
            (long long)SR_ * HID_, 1.f,
            nullptr, nullptr, nullptr, nullptr);
    }
    // 5. proj = O @ Wp + bp -> fp32
    {
        dim3 grid((DIM_ + 127) / 128, MROWS / 128, 1);
        h16_mma_gemm<0,512><<<grid, 256, SMEM>>>(
            o, wt + 3 * WSZ, bp, nullptr, p, nullptr, DIM_, 0, 0, 0, 1.f,
            nullptr, nullptr, nullptr, nullptr);
    }
    // 6. residual + LayerNorm
    residual_ln_kernel<<<MROWS, 256>>>(p, rgb, lng, lnb, gate, out);
}